// round 8
// baseline (speedup 1.0000x reference)
#include <cuda_runtime.h>
#include <math.h>

// Problem constants
constexpr int kN   = 512;    // atoms
constexpr int kE   = 4096;   // edges
constexpr int kH   = 128;    // hidden
constexpr int kHH  = 1024;   // H * NH
constexpr int kRBF = 64;

// ---------------------------------------------------------------------------
// Scratch (device globals; referenced ONLY from device code)
// ---------------------------------------------------------------------------
__device__ int   g_is64;                 // 1 if edge_indices buffer is int64
__device__ int   g_src[kE], g_tgt[kE];
__device__ __align__(16) float g_ai[kE * kH];
__device__ __align__(16) float g_aj[kE * kH];
__device__ __align__(16) float g_hi[kE * kH];
__device__ __align__(16) float g_hj[kE * kH];
__device__ __align__(16) float g_edgeij[kE * 3 * kH];
__device__ __align__(16) float g_rbf[kE * kRBF];
__device__ __align__(16) float g_Q[kE * kHH];
__device__ __align__(16) float g_Km[kE * kHH];
__device__ __align__(16) float g_V[kE * kHH];             // becomes feats
__device__ __align__(16) float g_logits[(size_t)kE * kE]; // 64 MB; becomes prod
__device__ __align__(16) float g_pf[kE * kHH];
__device__ __align__(16) float g_msg[kE * kH];
__device__ __align__(16) float g_agg[kN * kH];
__device__ __align__(16) float g_ln0[kN * kH];
__device__ __align__(16) float g_t1[kN * kH];
__device__ __align__(16) float g_t2[kN * kH];
__device__ __align__(16) float g_t3[kN * kH];

// ---------------------------------------------------------------------------
// Helpers
// ---------------------------------------------------------------------------
__device__ __forceinline__ float softplus_f(float x) {
    return fmaxf(x, 0.0f) + log1pf(expf(-fabsf(x)));
}

// ---------------------------------------------------------------------------
// Detect edge_indices element width. int64 values < 2^32 -> every odd 32-bit
// word is 0. Genuine int32 node ids (random in [0,512)) make that pattern
// vanishingly improbable across 32 samples. Deterministic per input.
// ---------------------------------------------------------------------------
__global__ void detect_idx_kernel(const void* __restrict__ ei) {
    const int* p = (const int*)ei;
    int looks64 = 1;
    for (int i = 0; i < 32; i++)
        if (p[2 * i + 1] != 0) looks64 = 0;
    g_is64 = looks64;
}

// ---------------------------------------------------------------------------
// prep: ai/aj = atom[tgt/src] + ew ; src/tgt as int32 ; rbf features
// grid: kE blocks x kH threads
// ---------------------------------------------------------------------------
__global__ void prep_kernel(const float* __restrict__ atom,
                            const float* __restrict__ pos,
                            const float* __restrict__ ew,
                            const void* __restrict__ ei) {
    int e = blockIdx.x, t = threadIdx.x;
    __shared__ float sdist;
    __shared__ int ssrc, stgt;
    if (t == 0) {
        int s, g;
        if (g_is64) {
            const long long* p = (const long long*)ei;
            s = (int)p[e];
            g = (int)p[kE + e];
        } else {
            const int* p = (const int*)ei;
            s = p[e];
            g = p[kE + e];
        }
        ssrc = s; stgt = g;
        g_src[e] = s; g_tgt[e] = g;
        float dx = pos[g * 3 + 0] - pos[s * 3 + 0];
        float dy = pos[g * 3 + 1] - pos[s * 3 + 1];
        float dz = pos[g * 3 + 2] - pos[s * 3 + 2];
        sdist = sqrtf(dx * dx + dy * dy + dz * dz);
    }
    __syncthreads();
    float w = ew[e];
    g_ai[e * kH + t] = atom[stgt * kH + t] + w;   // ai uses tgt
    g_aj[e * kH + t] = atom[ssrc * kH + t] + w;   // aj uses src
    if (t < kRBF) {
        float d  = sdist;
        float x  = d * 0.1f;                      // d / CUTOFF
        float x3 = x * x * x, x4 = x3 * x, x5 = x4 * x;
        float cut = (x < 1.0f) ? (1.0f - 6.0f * x5 + 15.0f * x4 - 10.0f * x3) : 0.0f;
        float em10 = expf(-10.0f);
        float step = (em10 - 1.0f) / 63.0f;
        float center = 1.0f + (float)t * step;
        float wd = 0.5f / ((1.0f - em10) / 64.0f);
        wd = wd * wd;
        float diff = expf(-d) - center;
        g_rbf[e * kRBF + t] = cut * expf(-wd * diff * diff);
    }
}

// ---------------------------------------------------------------------------
// edge_ij = [hi+hj, hi-hj, hi*hj]   grid: kE x kH
// ---------------------------------------------------------------------------
__global__ void edgeij_kernel() {
    int e = blockIdx.x, t = threadIdx.x;
    float hi = g_hi[e * kH + t];
    float hj = g_hj[e * kH + t];
    size_t b = (size_t)e * (3 * kH);
    g_edgeij[b + t]           = hi + hj;
    g_edgeij[b + kH + t]      = hi - hj;
    g_edgeij[b + 2 * kH + t]  = hi * hj;
}

// ---------------------------------------------------------------------------
// Generic fp32 GEMM body: C = alpha * A@B(^T) [+ C] [+ bias] [softplus]
// BM=BN=128, BK=16, 256 threads, 8x8 microtile.
// ---------------------------------------------------------------------------
template <bool TRANSB, int ACCUM, int ACT>
__device__ __forceinline__
void gemm_body(const float* __restrict__ A, const float* __restrict__ B,
               float* __restrict__ C, int M, int Nd, int Kd,
               const float* __restrict__ bias, float alpha) {
    constexpr int BM = 128, BN = 128, BK = 16;
    __shared__ __align__(16) float As[BK][BM + 4];
    __shared__ __align__(16) float Bs[BK][BN + 4];
    int tid = threadIdx.x;
    int tx = tid & 15, ty = tid >> 4;
    int m0 = blockIdx.y * BM, n0 = blockIdx.x * BN;
    float acc[8][8] = {};

    for (int k0 = 0; k0 < Kd; k0 += BK) {
        #pragma unroll
        for (int i = 0; i < 2; i++) {
            int f = tid + i * 256;
            int row = f >> 2, c4 = (f & 3) * 4;
            float4 av = *reinterpret_cast<const float4*>(
                &A[(size_t)(m0 + row) * Kd + k0 + c4]);
            As[c4 + 0][row] = av.x; As[c4 + 1][row] = av.y;
            As[c4 + 2][row] = av.z; As[c4 + 3][row] = av.w;
        }
        if (!TRANSB) {
            #pragma unroll
            for (int i = 0; i < 2; i++) {
                int f = tid + i * 256;
                int row = f >> 5, c4 = (f & 31) * 4;
                float4 bv = *reinterpret_cast<const float4*>(
                    &B[(size_t)(k0 + row) * Nd + n0 + c4]);
                *reinterpret_cast<float4*>(&Bs[row][c4]) = bv;
            }
        } else {
            #pragma unroll
            for (int i = 0; i < 2; i++) {
                int f = tid + i * 256;
                int row = f >> 2, c4 = (f & 3) * 4;
                float4 bv = *reinterpret_cast<const float4*>(
                    &B[(size_t)(n0 + row) * Kd + k0 + c4]);
                Bs[c4 + 0][row] = bv.x; Bs[c4 + 1][row] = bv.y;
                Bs[c4 + 2][row] = bv.z; Bs[c4 + 3][row] = bv.w;
            }
        }
        __syncthreads();
        #pragma unroll
        for (int k = 0; k < BK; k++) {
            float4 a0 = *reinterpret_cast<const float4*>(&As[k][ty * 8]);
            float4 a1 = *reinterpret_cast<const float4*>(&As[k][ty * 8 + 4]);
            float4 b0 = *reinterpret_cast<const float4*>(&Bs[k][tx * 8]);
            float4 b1 = *reinterpret_cast<const float4*>(&Bs[k][tx * 8 + 4]);
            float a[8] = {a0.x, a0.y, a0.z, a0.w, a1.x, a1.y, a1.z, a1.w};
            float b[8] = {b0.x, b0.y, b0.z, b0.w, b1.x, b1.y, b1.z, b1.w};
            #pragma unroll
            for (int i = 0; i < 8; i++)
                #pragma unroll
                for (int j = 0; j < 8; j++)
                    acc[i][j] = fmaf(a[i], b[j], acc[i][j]);
        }
        __syncthreads();
    }

    #pragma unroll
    for (int i = 0; i < 8; i++) {
        int m = m0 + ty * 8 + i;
        #pragma unroll
        for (int j = 0; j < 8; j++) {
            int n = n0 + tx * 8 + j;
            float v = alpha * acc[i][j];
            if (ACCUM) v += C[(size_t)m * Nd + n];
            if (bias)  v += bias[n];
            if (ACT)   v = softplus_f(v);
            C[(size_t)m * Nd + n] = v;
        }
    }
}

// ---- GEMM wrappers: bind device-symbol operands in device code ------------
__global__ __launch_bounds__(256) void k_gemm_Q(const float* __restrict__ W) {
    gemm_body<false, 0, 0>(g_ai, W, g_Q, kE, kHH, kH, nullptr, 1.0f);
}
__global__ __launch_bounds__(256) void k_gemm_K(const float* __restrict__ W) {
    gemm_body<false, 0, 0>(g_ai, W, g_Km, kE, kHH, kH, nullptr, 1.0f);
}
__global__ __launch_bounds__(256) void k_gemm_V(const float* __restrict__ W) {
    gemm_body<false, 0, 0>(g_ai, W, g_V, kE, kHH, kH, nullptr, 1.0f);
}
__global__ __launch_bounds__(256) void k_gemm_hi(const float* __restrict__ W,
                                                 const float* __restrict__ b) {
    gemm_body<false, 0, 0>(g_ai, W, g_hi, kE, kH, kH, b, 1.0f);
}
__global__ __launch_bounds__(256) void k_gemm_hj(const float* __restrict__ W,
                                                 const float* __restrict__ b) {
    gemm_body<false, 0, 0>(g_aj, W, g_hj, kE, kH, kH, b, 1.0f);
}
__global__ __launch_bounds__(256) void k_gemm_logits() {
    const float scale = 0.08838834764831845f;  // 128^-0.5
    gemm_body<true, 0, 0>(g_Q, g_Km, g_logits, kE, kE, kHH, nullptr, scale);
}
__global__ __launch_bounds__(256) void k_gemm_el(const float* __restrict__ W) {
    gemm_body<false, 1, 0>(g_edgeij, W, g_V, kE, kHH, 3 * kH, nullptr, 1.0f);
}
__global__ __launch_bounds__(256) void k_gemm_rl(const float* __restrict__ W) {
    gemm_body<false, 1, 0>(g_rbf, W, g_V, kE, kHH, kRBF, nullptr, 1.0f);
}
__global__ __launch_bounds__(256) void k_gemm_pf() {
    gemm_body<false, 0, 0>(g_logits, g_V, g_pf, kE, kHH, kE, nullptr, 1.0f);
}
__global__ __launch_bounds__(256) void k_gemm_msg(const float* __restrict__ W,
                                                  const float* __restrict__ b) {
    gemm_body<false, 0, 0>(g_pf, W, g_msg, kE, kH, kHH, b, 1.0f);
}
__global__ __launch_bounds__(256) void k_gemm_f1(const float* __restrict__ W,
                                                 const float* __restrict__ b) {
    gemm_body<false, 0, 1>(g_ln0, W, g_t1, kN, kH, kH, b, 1.0f);
}
__global__ __launch_bounds__(256) void k_gemm_f2(const float* __restrict__ W,
                                                 const float* __restrict__ b) {
    gemm_body<false, 0, 1>(g_t1, W, g_t2, kN, kH, kH, b, 1.0f);
}
__global__ __launch_bounds__(256) void k_gemm_f3(const float* __restrict__ W,
                                                 const float* __restrict__ b) {
    gemm_body<false, 0, 1>(g_t2, W, g_t3, kN, kH, kH, b, 1.0f);
}

// ---------------------------------------------------------------------------
// Per-row segmented softmax over columns, groups = src[col]. In-place.
// grid: kE blocks x 256 threads
// ---------------------------------------------------------------------------
__global__ void softmax_kernel() {
    __shared__ unsigned int smax[kN];
    __shared__ float ssum[kN];
    __shared__ int ssrc[kE];
    const int T = 256;
    int row = blockIdx.x, t = threadIdx.x;
    for (int i = t; i < kN; i += T) { smax[i] = 0u; ssum[i] = 0.0f; }
    for (int i = t; i < kE; i += T) ssrc[i] = g_src[i];
    __syncthreads();
    float* L = g_logits + (size_t)row * kE;
    // pass 1: segmented max (exact, order-independent; flipped-uint encoding)
    for (int b = t; b < kE; b += T) {
        unsigned u = __float_as_uint(L[b]);
        u = (u & 0x80000000u) ? ~u : (u | 0x80000000u);
        atomicMax(&smax[ssrc[b]], u);
    }
    __syncthreads();
    // pass 2: segmented sum of exp
    for (int b = t; b < kE; b += T) {
        unsigned u = smax[ssrc[b]];
        float m = (u & 0x80000000u) ? __uint_as_float(u & 0x7FFFFFFFu)
                                    : __uint_as_float(~u);
        atomicAdd(&ssum[ssrc[b]], __expf(L[b] - m));
    }
    __syncthreads();
    // pass 3: normalize in-place
    for (int b = t; b < kE; b += T) {
        int s = ssrc[b];
        unsigned u = smax[s];
        float m = (u & 0x80000000u) ? __uint_as_float(u & 0x7FFFFFFFu)
                                    : __uint_as_float(~u);
        L[b] = __expf(L[b] - m) / ssum[s];
    }
}

// feats init: V += el_b + rl_b (broadcast over columns)
__global__ void feats_bias_kernel(const float* __restrict__ el_b,
                                  const float* __restrict__ rl_b) {
    int i = blockIdx.x * blockDim.x + threadIdx.x;
    int c = i & (kHH - 1);
    g_V[i] += el_b[c] + rl_b[c];
}

__global__ void zero_agg_kernel() {
    int i = blockIdx.x * blockDim.x + threadIdx.x;
    g_agg[i] = 0.0f;
}

// segment_sum(msg, tgt) via atomics. grid kE x kH
__global__ void scatter_kernel() {
    int e = blockIdx.x, t = threadIdx.x;
    atomicAdd(&g_agg[g_tgt[e] * kH + t], g_msg[e * kH + t]);
}

// ---------------------------------------------------------------------------
// LayerNorm over H=128, one block (128 threads) per node, two-pass.
// ---------------------------------------------------------------------------
__device__ __forceinline__ float blockSum128(float v) {
    __shared__ float sw[4];
    __syncthreads();
    int lane = threadIdx.x & 31, wid = threadIdx.x >> 5;
    #pragma unroll
    for (int o = 16; o; o >>= 1) v += __shfl_down_sync(0xffffffffu, v, o);
    if (lane == 0) sw[wid] = v;
    __syncthreads();
    if (threadIdx.x == 0) sw[0] = sw[0] + sw[1] + sw[2] + sw[3];
    __syncthreads();
    return sw[0];
}

__device__ __forceinline__ void ln_body(const float* __restrict__ in,
                                        float* __restrict__ out,
                                        const float* __restrict__ gw,
                                        const float* __restrict__ gb) {
    int n = blockIdx.x, t = threadIdx.x;
    float x = in[n * kH + t];
    float mu = blockSum128(x) * (1.0f / kH);
    float d = x - mu;
    float var = blockSum128(d * d) * (1.0f / kH);
    out[n * kH + t] = d * rsqrtf(var + 1e-5f) * gw[t] + gb[t];
}

__global__ void k_ln_agg(const float* __restrict__ gw, const float* __restrict__ gb) {
    ln_body(g_agg, g_ln0, gw, gb);
}
__global__ void k_ln_out(float* __restrict__ out,
                         const float* __restrict__ gw, const float* __restrict__ gb) {
    ln_body(g_t3, out, gw, gb);
}

// ---------------------------------------------------------------------------
// Launch
// ---------------------------------------------------------------------------
extern "C" void kernel_launch(void* const* d_in, const int* in_sizes, int n_in,
                              void* d_out, int out_size) {
    const float* atom  = (const float*)d_in[0];
    const float* pos   = (const float*)d_in[1];
    const float* ew    = (const float*)d_in[2];
    const void*  ei    = d_in[3];
    const float* Wq    = (const float*)d_in[4];
    const float* Wk    = (const float*)d_in[5];
    const float* Wv    = (const float*)d_in[6];
    const float* li_w  = (const float*)d_in[7];
    const float* li_b  = (const float*)d_in[8];
    const float* lj_w  = (const float*)d_in[9];
    const float* lj_b  = (const float*)d_in[10];
    const float* el_w  = (const float*)d_in[11];
    const float* el_b  = (const float*)d_in[12];
    const float* rl_w  = (const float*)d_in[13];
    const float* rl_b  = (const float*)d_in[14];
    const float* ol_w  = (const float*)d_in[15];
    const float* ol_b  = (const float*)d_in[16];
    const float* ln_g  = (const float*)d_in[17];
    const float* ln_b  = (const float*)d_in[18];
    const float* f1_w  = (const float*)d_in[19];
    const float* f1_b  = (const float*)d_in[20];
    const float* f2_w  = (const float*)d_in[21];
    const float* f2_b  = (const float*)d_in[22];
    const float* f3_w  = (const float*)d_in[23];
    const float* f3_b  = (const float*)d_in[24];
    float* out = (float*)d_out;

    detect_idx_kernel<<<1, 1>>>(ei);
    prep_kernel<<<kE, kH>>>(atom, pos, ew, ei);

    dim3 gQKV(kHH / 128, kE / 128);   // 8 x 32
    k_gemm_Q<<<gQKV, 256>>>(Wq);
    k_gemm_K<<<gQKV, 256>>>(Wk);
    k_gemm_V<<<gQKV, 256>>>(Wv);

    dim3 gH(kH / 128, kE / 128);      // 1 x 32
    k_gemm_hi<<<gH, 256>>>(li_w, li_b);
    k_gemm_hj<<<gH, 256>>>(lj_w, lj_b);

    edgeij_kernel<<<kE, kH>>>();

    // logits = scale * Q @ K^T   (E x E, K=1024)
    dim3 gL(kE / 128, kE / 128);      // 32 x 32
    k_gemm_logits<<<gL, 256>>>();

    softmax_kernel<<<kE, 256>>>();

    // feats = V + el_b + rl_b + edge_ij@el_w + rbf@rl_w  (built in g_V)
    feats_bias_kernel<<<(kE * kHH) / 256, 256>>>(el_b, rl_b);
    k_gemm_el<<<gQKV, 256>>>(el_w);
    k_gemm_rl<<<gQKV, 256>>>(rl_w);

    // pf = prod @ feats   (E x HH, K = E)
    k_gemm_pf<<<gQKV, 256>>>();

    // msg = pf @ ol_w + ol_b
    k_gemm_msg<<<gH, 256>>>(ol_w, ol_b);

    zero_agg_kernel<<<(kN * kH) / 256, 256>>>();
    scatter_kernel<<<kE, kH>>>();

    k_ln_agg<<<kN, kH>>>(ln_g, ln_b);

    dim3 gF(kH / 128, kN / 128);      // 1 x 4
    k_gemm_f1<<<gF, 256>>>(f1_w, f1_b);
    k_gemm_f2<<<gF, 256>>>(f2_w, f2_b);
    k_gemm_f3<<<gF, 256>>>(f3_w, f3_b);

    k_ln_out<<<kN, kH>>>(out, ln_g, ln_b);
}

// round 10
// speedup vs baseline: 1.5792x; 1.5792x over previous
#include <cuda_runtime.h>
#include <cuda_bf16.h>
#include <math.h>
#include <stdint.h>

// Problem constants
constexpr int kN   = 512;    // atoms
constexpr int kE   = 4096;   // edges
constexpr int kH   = 128;    // hidden
constexpr int kHH  = 1024;   // H * NH
constexpr int kRBF = 64;

// ---------------------------------------------------------------------------
// Scratch (device globals; referenced ONLY from device code)
// ---------------------------------------------------------------------------
__device__ int   g_is64;
__device__ int   g_src[kE], g_tgt[kE];
__device__ __align__(16) float g_ai[kE * kH];
__device__ __align__(16) float g_aj[kE * kH];
__device__ __align__(16) float g_hi[kE * kH];
__device__ __align__(16) float g_hj[kE * kH];
__device__ __align__(16) float g_edgeij[kE * 3 * kH];
__device__ __align__(16) float g_rbf[kE * kRBF];
__device__ __align__(16) float g_V[kE * kHH];             // becomes feats
__device__ __align__(16) float g_logits[(size_t)kE * kE]; // fp32 logits
__device__ __align__(16) float g_pf[kE * kHH];
__device__ __align__(16) float g_msg[kE * kH];
__device__ __align__(16) float g_agg[kN * kH];
__device__ __align__(16) float g_ln0[kN * kH];
__device__ __align__(16) float g_t1[kN * kH];
__device__ __align__(16) float g_t2[kN * kH];
__device__ __align__(16) float g_t3[kN * kH];

// split-bf16 operands for tensor-core GEMMs
__device__ __align__(16) __nv_bfloat16 g_Qhi[kE * kHH];
__device__ __align__(16) __nv_bfloat16 g_Qlo[kE * kHH];
__device__ __align__(16) __nv_bfloat16 g_Khi[kE * kHH];
__device__ __align__(16) __nv_bfloat16 g_Klo[kE * kHH];
__device__ __align__(16) __nv_bfloat16 g_Phi[(size_t)kE * kE];
__device__ __align__(16) __nv_bfloat16 g_Plo[(size_t)kE * kE];
__device__ __align__(16) __nv_bfloat16 g_FThi[(size_t)kHH * kE];
__device__ __align__(16) __nv_bfloat16 g_FTlo[(size_t)kHH * kE];

// ---------------------------------------------------------------------------
// Helpers
// ---------------------------------------------------------------------------
__device__ __forceinline__ float softplus_f(float x) {
    return fmaxf(x, 0.0f) + log1pf(expf(-fabsf(x)));
}
__device__ __forceinline__ void split2(float v, __nv_bfloat16& hi, __nv_bfloat16& lo) {
    hi = __float2bfloat16(v);
    lo = __float2bfloat16(v - __bfloat162float(hi));
}
__device__ __forceinline__ uint32_t smem_u32(const void* p) {
    uint32_t a;
    asm("{ .reg .u64 t; cvta.to.shared.u64 t, %1; cvt.u32.u64 %0, t; }"
        : "=r"(a) : "l"(p));
    return a;
}

// ---- warp-MMA primitives (valid on baseline compute_103) -------------------
__device__ __forceinline__ void ldm_x4(uint32_t* r, uint32_t a) {
    asm volatile("ldmatrix.sync.aligned.m8n8.x4.shared.b16 {%0,%1,%2,%3}, [%4];"
                 : "=r"(r[0]), "=r"(r[1]), "=r"(r[2]), "=r"(r[3]) : "r"(a));
}
__device__ __forceinline__ void ldm_x2(uint32_t* r, uint32_t a) {
    asm volatile("ldmatrix.sync.aligned.m8n8.x2.shared.b16 {%0,%1}, [%2];"
                 : "=r"(r[0]), "=r"(r[1]) : "r"(a));
}
__device__ __forceinline__ void mma16816(float* d, const uint32_t* a, const uint32_t* b) {
    asm volatile(
        "mma.sync.aligned.m16n8k16.row.col.f32.bf16.bf16.f32 "
        "{%0,%1,%2,%3}, {%4,%5,%6,%7}, {%8,%9}, {%0,%1,%2,%3};"
        : "+f"(d[0]), "+f"(d[1]), "+f"(d[2]), "+f"(d[3])
        : "r"(a[0]), "r"(a[1]), "r"(a[2]), "r"(a[3]), "r"(b[0]), "r"(b[1]));
}

// ---------------------------------------------------------------------------
// Split-bf16 tensor-core GEMM: C[M x N] = alpha * sum_k A[m][k]*B[n][k]
// A,B as (hi,lo) bf16 K-major (row stride Kd). CTA: 128x128, 256 threads,
// BK=32, warp grid 2x4 (warp tile 64x32). 3 MMAs per tile (hi*hi+lo*hi+hi*lo).
// ---------------------------------------------------------------------------
constexpr int SPITCH = 40;   // bf16 elems per SMEM row (32 + 8 pad = 80 B)

__device__ __forceinline__ void mma_gemm_body(
    const __nv_bfloat16* __restrict__ Ahi, const __nv_bfloat16* __restrict__ Alo,
    const __nv_bfloat16* __restrict__ Bhi, const __nv_bfloat16* __restrict__ Blo,
    float* __restrict__ C, int Kd, int ldC, float alpha)
{
    __shared__ __align__(16) __nv_bfloat16 sAhi[128][SPITCH];
    __shared__ __align__(16) __nv_bfloat16 sAlo[128][SPITCH];
    __shared__ __align__(16) __nv_bfloat16 sBhi[128][SPITCH];
    __shared__ __align__(16) __nv_bfloat16 sBlo[128][SPITCH];

    int tid = threadIdx.x;
    int wid = tid >> 5, lane = tid & 31;
    int wm = wid & 1, wn = wid >> 1;            // 2 x 4 warp grid
    int m0 = blockIdx.y * 128, n0 = blockIdx.x * 128;

    float acc[4][4][4] = {};                    // [mt][nt][frag]

    for (int k0 = 0; k0 < Kd; k0 += 32) {
        // Global -> SMEM: each matrix 128 rows x 64 B (4 x uint4 per row)
        #pragma unroll
        for (int i = 0; i < 2; i++) {
            int idx = tid + i * 256;            // 0..511
            int row = idx >> 2, q = idx & 3;
            size_t goffA = (size_t)(m0 + row) * Kd + k0;
            size_t goffB = (size_t)(n0 + row) * Kd + k0;
            *reinterpret_cast<uint4*>(&sAhi[row][q * 8]) =
                *(reinterpret_cast<const uint4*>(Ahi + goffA) + q);
            *reinterpret_cast<uint4*>(&sAlo[row][q * 8]) =
                *(reinterpret_cast<const uint4*>(Alo + goffA) + q);
            *reinterpret_cast<uint4*>(&sBhi[row][q * 8]) =
                *(reinterpret_cast<const uint4*>(Bhi + goffB) + q);
            *reinterpret_cast<uint4*>(&sBlo[row][q * 8]) =
                *(reinterpret_cast<const uint4*>(Blo + goffB) + q);
        }
        __syncthreads();

        #pragma unroll
        for (int ks = 0; ks < 2; ks++) {        // two k16 substeps
            uint32_t ahi[4][4], alo[4][4];
            #pragma unroll
            for (int mt = 0; mt < 4; mt++) {
                int r  = wm * 64 + mt * 16 + (lane & 15);
                int cb = ks * 16 + (lane >> 4) * 8;
                ldm_x4(ahi[mt], smem_u32(&sAhi[r][cb]));
                ldm_x4(alo[mt], smem_u32(&sAlo[r][cb]));
            }
            uint32_t bhi[4][2], blo[4][2];
            #pragma unroll
            for (int nt = 0; nt < 4; nt++) {
                int r  = wn * 32 + nt * 8 + (lane & 7);
                int cb = ks * 16 + ((lane >> 3) & 1) * 8;
                ldm_x2(bhi[nt], smem_u32(&sBhi[r][cb]));
                ldm_x2(blo[nt], smem_u32(&sBlo[r][cb]));
            }
            #pragma unroll
            for (int mt = 0; mt < 4; mt++)
                #pragma unroll
                for (int nt = 0; nt < 4; nt++) {
                    mma16816(acc[mt][nt], ahi[mt], bhi[nt]);
                    mma16816(acc[mt][nt], alo[mt], bhi[nt]);
                    mma16816(acc[mt][nt], ahi[mt], blo[nt]);
                }
        }
        __syncthreads();
    }

    // Epilogue: c0,c1 at (row, col..col+1); c2,c3 at (row+8, ...)
    int gr = lane >> 2, gc = (lane & 3) * 2;
    #pragma unroll
    for (int mt = 0; mt < 4; mt++) {
        int row = m0 + wm * 64 + mt * 16 + gr;
        #pragma unroll
        for (int nt = 0; nt < 4; nt++) {
            int col = n0 + wn * 32 + nt * 8 + gc;
            float2 v0 = make_float2(alpha * acc[mt][nt][0], alpha * acc[mt][nt][1]);
            float2 v1 = make_float2(alpha * acc[mt][nt][2], alpha * acc[mt][nt][3]);
            *reinterpret_cast<float2*>(C + (size_t)row * ldC + col)       = v0;
            *reinterpret_cast<float2*>(C + (size_t)(row + 8) * ldC + col) = v1;
        }
    }
}

__global__ void __launch_bounds__(256) k_mma_logits() {
    mma_gemm_body(g_Qhi, g_Qlo, g_Khi, g_Klo, g_logits, kHH, kE,
                  0.08838834764831845f);
}
__global__ void __launch_bounds__(256) k_mma_pf() {
    mma_gemm_body(g_Phi, g_Plo, g_FThi, g_FTlo, g_pf, kE, kHH, 1.0f);
}

// ---------------------------------------------------------------------------
// Detect edge_indices element width (int64 vs int32).
// ---------------------------------------------------------------------------
__global__ void detect_idx_kernel(const void* __restrict__ ei) {
    const int* p = (const int*)ei;
    int looks64 = 1;
    for (int i = 0; i < 32; i++)
        if (p[2 * i + 1] != 0) looks64 = 0;
    g_is64 = looks64;
}

// ---------------------------------------------------------------------------
// prep: ai/aj = atom[tgt/src] + ew ; rbf features.  grid kE x kH
// ---------------------------------------------------------------------------
__global__ void prep_kernel(const float* __restrict__ atom,
                            const float* __restrict__ pos,
                            const float* __restrict__ ew,
                            const void* __restrict__ ei) {
    int e = blockIdx.x, t = threadIdx.x;
    __shared__ float sdist;
    __shared__ int ssrc, stgt;
    if (t == 0) {
        int s, g;
        if (g_is64) {
            const long long* p = (const long long*)ei;
            s = (int)p[e];  g = (int)p[kE + e];
        } else {
            const int* p = (const int*)ei;
            s = p[e];  g = p[kE + e];
        }
        ssrc = s; stgt = g;
        g_src[e] = s; g_tgt[e] = g;
        float dx = pos[g * 3 + 0] - pos[s * 3 + 0];
        float dy = pos[g * 3 + 1] - pos[s * 3 + 1];
        float dz = pos[g * 3 + 2] - pos[s * 3 + 2];
        sdist = sqrtf(dx * dx + dy * dy + dz * dz);
    }
    __syncthreads();
    float w = ew[e];
    g_ai[e * kH + t] = atom[stgt * kH + t] + w;
    g_aj[e * kH + t] = atom[ssrc * kH + t] + w;
    if (t < kRBF) {
        float d  = sdist;
        float x  = d * 0.1f;
        float x3 = x * x * x, x4 = x3 * x, x5 = x4 * x;
        float cut = (x < 1.0f) ? (1.0f - 6.0f * x5 + 15.0f * x4 - 10.0f * x3) : 0.0f;
        float em10 = expf(-10.0f);
        float step = (em10 - 1.0f) / 63.0f;
        float center = 1.0f + (float)t * step;
        float wd = 0.5f / ((1.0f - em10) / 64.0f);
        wd = wd * wd;
        float diff = expf(-d) - center;
        g_rbf[e * kRBF + t] = cut * expf(-wd * diff * diff);
    }
}

// edge_ij = [hi+hj, hi-hj, hi*hj]   grid: kE x kH
__global__ void edgeij_kernel() {
    int e = blockIdx.x, t = threadIdx.x;
    float hi = g_hi[e * kH + t];
    float hj = g_hj[e * kH + t];
    size_t b = (size_t)e * (3 * kH);
    g_edgeij[b + t]          = hi + hj;
    g_edgeij[b + kH + t]     = hi - hj;
    g_edgeij[b + 2 * kH + t] = hi * hj;
}

// ---------------------------------------------------------------------------
// FFMA GEMM body (small GEMMs): C = alpha*A@B [+C][+bias][softplus] or SPLIT
// BM=BN=128, BK=16, 256 threads, 8x8 microtile.
// ---------------------------------------------------------------------------
template <int ACCUM, int ACT, int SPLIT>
__device__ __forceinline__
void gemm_body(const float* __restrict__ A, const float* __restrict__ B,
               float* __restrict__ C, int M, int Nd, int Kd,
               const float* __restrict__ bias, float alpha,
               __nv_bfloat16* __restrict__ Chi, __nv_bfloat16* __restrict__ Clo) {
    constexpr int BM = 128, BN = 128, BK = 16;
    __shared__ __align__(16) float As[BK][BM + 4];
    __shared__ __align__(16) float Bs[BK][BN + 4];
    int tid = threadIdx.x;
    int tx = tid & 15, ty = tid >> 4;
    int m0 = blockIdx.y * BM, n0 = blockIdx.x * BN;
    float acc[8][8] = {};

    for (int k0 = 0; k0 < Kd; k0 += BK) {
        #pragma unroll
        for (int i = 0; i < 2; i++) {
            int f = tid + i * 256;
            int row = f >> 2, c4 = (f & 3) * 4;
            float4 av = *reinterpret_cast<const float4*>(
                &A[(size_t)(m0 + row) * Kd + k0 + c4]);
            As[c4 + 0][row] = av.x; As[c4 + 1][row] = av.y;
            As[c4 + 2][row] = av.z; As[c4 + 3][row] = av.w;
        }
        #pragma unroll
        for (int i = 0; i < 2; i++) {
            int f = tid + i * 256;
            int row = f >> 5, c4 = (f & 31) * 4;
            float4 bv = *reinterpret_cast<const float4*>(
                &B[(size_t)(k0 + row) * Nd + n0 + c4]);
            *reinterpret_cast<float4*>(&Bs[row][c4]) = bv;
        }
        __syncthreads();
        #pragma unroll
        for (int k = 0; k < BK; k++) {
            float4 a0 = *reinterpret_cast<const float4*>(&As[k][ty * 8]);
            float4 a1 = *reinterpret_cast<const float4*>(&As[k][ty * 8 + 4]);
            float4 b0 = *reinterpret_cast<const float4*>(&Bs[k][tx * 8]);
            float4 b1 = *reinterpret_cast<const float4*>(&Bs[k][tx * 8 + 4]);
            float a[8] = {a0.x, a0.y, a0.z, a0.w, a1.x, a1.y, a1.z, a1.w};
            float b[8] = {b0.x, b0.y, b0.z, b0.w, b1.x, b1.y, b1.z, b1.w};
            #pragma unroll
            for (int i = 0; i < 8; i++)
                #pragma unroll
                for (int j = 0; j < 8; j++)
                    acc[i][j] = fmaf(a[i], b[j], acc[i][j]);
        }
        __syncthreads();
    }

    #pragma unroll
    for (int i = 0; i < 8; i++) {
        int m = m0 + ty * 8 + i;
        #pragma unroll
        for (int j = 0; j < 8; j++) {
            int n = n0 + tx * 8 + j;
            float v = alpha * acc[i][j];
            if (ACCUM) v += C[(size_t)m * Nd + n];
            if (bias)  v += bias[n];
            if (ACT)   v = softplus_f(v);
            if (SPLIT) {
                __nv_bfloat16 h, l;
                split2(v, h, l);
                Chi[(size_t)m * Nd + n] = h;
                Clo[(size_t)m * Nd + n] = l;
            } else {
                C[(size_t)m * Nd + n] = v;
            }
        }
    }
}

// ---- GEMM wrappers --------------------------------------------------------
__global__ __launch_bounds__(256) void k_gemm_Q(const float* __restrict__ W) {
    gemm_body<0, 0, 1>(g_ai, W, nullptr, kE, kHH, kH, nullptr, 1.0f, g_Qhi, g_Qlo);
}
__global__ __launch_bounds__(256) void k_gemm_K(const float* __restrict__ W) {
    gemm_body<0, 0, 1>(g_ai, W, nullptr, kE, kHH, kH, nullptr, 1.0f, g_Khi, g_Klo);
}
__global__ __launch_bounds__(256) void k_gemm_V(const float* __restrict__ W) {
    gemm_body<0, 0, 0>(g_ai, W, g_V, kE, kHH, kH, nullptr, 1.0f, nullptr, nullptr);
}
__global__ __launch_bounds__(256) void k_gemm_hi(const float* __restrict__ W,
                                                 const float* __restrict__ b) {
    gemm_body<0, 0, 0>(g_ai, W, g_hi, kE, kH, kH, b, 1.0f, nullptr, nullptr);
}
__global__ __launch_bounds__(256) void k_gemm_hj(const float* __restrict__ W,
                                                 const float* __restrict__ b) {
    gemm_body<0, 0, 0>(g_aj, W, g_hj, kE, kH, kH, b, 1.0f, nullptr, nullptr);
}
__global__ __launch_bounds__(256) void k_gemm_el(const float* __restrict__ W) {
    gemm_body<1, 0, 0>(g_edgeij, W, g_V, kE, kHH, 3 * kH, nullptr, 1.0f, nullptr, nullptr);
}
__global__ __launch_bounds__(256) void k_gemm_rl(const float* __restrict__ W) {
    gemm_body<1, 0, 0>(g_rbf, W, g_V, kE, kHH, kRBF, nullptr, 1.0f, nullptr, nullptr);
}
__global__ __launch_bounds__(256) void k_gemm_msg(const float* __restrict__ W,
                                                  const float* __restrict__ b) {
    gemm_body<0, 0, 0>(g_pf, W, g_msg, kE, kH, kHH, b, 1.0f, nullptr, nullptr);
}
__global__ __launch_bounds__(256) void k_gemm_f1(const float* __restrict__ W,
                                                 const float* __restrict__ b) {
    gemm_body<0, 1, 0>(g_ln0, W, g_t1, kN, kH, kH, b, 1.0f, nullptr, nullptr);
}
__global__ __launch_bounds__(256) void k_gemm_f2(const float* __restrict__ W,
                                                 const float* __restrict__ b) {
    gemm_body<0, 1, 0>(g_t1, W, g_t2, kN, kH, kH, b, 1.0f, nullptr, nullptr);
}
__global__ __launch_bounds__(256) void k_gemm_f3(const float* __restrict__ W,
                                                 const float* __restrict__ b) {
    gemm_body<0, 1, 0>(g_t2, W, g_t3, kN, kH, kH, b, 1.0f, nullptr, nullptr);
}

// ---------------------------------------------------------------------------
// Per-row segmented softmax over columns, groups = src[col].
// Pass 3 writes split-bf16 P directly. grid: kE x 256
// ---------------------------------------------------------------------------
__global__ void softmax_kernel() {
    __shared__ unsigned int smax[kN];
    __shared__ float ssum[kN];
    __shared__ int ssrc[kE];
    const int T = 256;
    int row = blockIdx.x, t = threadIdx.x;
    for (int i = t; i < kN; i += T) { smax[i] = 0u; ssum[i] = 0.0f; }
    for (int i = t; i < kE; i += T) ssrc[i] = g_src[i];
    __syncthreads();
    const float* L = g_logits + (size_t)row * kE;
    for (int b = t; b < kE; b += T) {
        unsigned u = __float_as_uint(L[b]);
        u = (u & 0x80000000u) ? ~u : (u | 0x80000000u);
        atomicMax(&smax[ssrc[b]], u);
    }
    __syncthreads();
    for (int b = t; b < kE; b += T) {
        unsigned u = smax[ssrc[b]];
        float m = (u & 0x80000000u) ? __uint_as_float(u & 0x7FFFFFFFu)
                                    : __uint_as_float(~u);
        atomicAdd(&ssum[ssrc[b]], __expf(L[b] - m));
    }
    __syncthreads();
    for (int b = t; b < kE; b += T) {
        int s = ssrc[b];
        unsigned u = smax[s];
        float m = (u & 0x80000000u) ? __uint_as_float(u & 0x7FFFFFFFu)
                                    : __uint_as_float(~u);
        float p = __expf(L[b] - m) / ssum[s];
        __nv_bfloat16 h, l;
        split2(p, h, l);
        g_Phi[(size_t)row * kE + b] = h;
        g_Plo[(size_t)row * kE + b] = l;
    }
}

// feats init: V += el_b + rl_b (broadcast over columns)
__global__ void feats_bias_kernel(const float* __restrict__ el_b,
                                  const float* __restrict__ rl_b) {
    int i = blockIdx.x * blockDim.x + threadIdx.x;
    int c = i & (kHH - 1);
    g_V[i] += el_b[c] + rl_b[c];
}

// F [kE x kHH] float -> FT hi/lo [kHH x kE] bf16 (tiled transpose + split)
__global__ void k_transpose_split_F() {
    __shared__ float tile[32][33];
    int tx = threadIdx.x, ty = threadIdx.y;   // 32 x 8
    int n0 = blockIdx.x * 32;                 // along kHH
    int k0 = blockIdx.y * 32;                 // along kE
    #pragma unroll
    for (int i = 0; i < 4; i++)
        tile[ty + i * 8][tx] = g_V[(size_t)(k0 + ty + i * 8) * kHH + n0 + tx];
    __syncthreads();
    #pragma unroll
    for (int i = 0; i < 4; i++) {
        int n = n0 + ty + i * 8;
        int k = k0 + tx;
        float v = tile[tx][ty + i * 8];
        __nv_bfloat16 h, l;
        split2(v, h, l);
        g_FThi[(size_t)n * kE + k] = h;
        g_FTlo[(size_t)n * kE + k] = l;
    }
}

__global__ void zero_agg_kernel() {
    int i = blockIdx.x * blockDim.x + threadIdx.x;
    g_agg[i] = 0.0f;
}

// segment_sum(msg, tgt) via atomics. grid kE x kH
__global__ void scatter_kernel() {
    int e = blockIdx.x, t = threadIdx.x;
    atomicAdd(&g_agg[g_tgt[e] * kH + t], g_msg[e * kH + t]);
}

// ---------------------------------------------------------------------------
// LayerNorm over H=128, one block (128 threads) per node.
// ---------------------------------------------------------------------------
__device__ __forceinline__ float blockSum128(float v) {
    __shared__ float sw[4];
    __syncthreads();
    int lane = threadIdx.x & 31, wid = threadIdx.x >> 5;
    #pragma unroll
    for (int o = 16; o; o >>= 1) v += __shfl_down_sync(0xffffffffu, v, o);
    if (lane == 0) sw[wid] = v;
    __syncthreads();
    if (threadIdx.x == 0) sw[0] = sw[0] + sw[1] + sw[2] + sw[3];
    __syncthreads();
    return sw[0];
}

__device__ __forceinline__ void ln_body(const float* __restrict__ in,
                                        float* __restrict__ out,
                                        const float* __restrict__ gw,
                                        const float* __restrict__ gb) {
    int n = blockIdx.x, t = threadIdx.x;
    float x = in[n * kH + t];
    float mu = blockSum128(x) * (1.0f / kH);
    float d = x - mu;
    float var = blockSum128(d * d) * (1.0f / kH);
    out[n * kH + t] = d * rsqrtf(var + 1e-5f) * gw[t] + gb[t];
}

__global__ void k_ln_agg(const float* __restrict__ gw, const float* __restrict__ gb) {
    ln_body(g_agg, g_ln0, gw, gb);
}
__global__ void k_ln_out(float* __restrict__ out,
                         const float* __restrict__ gw, const float* __restrict__ gb) {
    ln_body(g_t3, out, gw, gb);
}

// ---------------------------------------------------------------------------
// Launch
// ---------------------------------------------------------------------------
extern "C" void kernel_launch(void* const* d_in, const int* in_sizes, int n_in,
                              void* d_out, int out_size) {
    const float* atom  = (const float*)d_in[0];
    const float* pos   = (const float*)d_in[1];
    const float* ew    = (const float*)d_in[2];
    const void*  ei    = d_in[3];
    const float* Wq    = (const float*)d_in[4];
    const float* Wk    = (const float*)d_in[5];
    const float* Wv    = (const float*)d_in[6];
    const float* li_w  = (const float*)d_in[7];
    const float* li_b  = (const float*)d_in[8];
    const float* lj_w  = (const float*)d_in[9];
    const float* lj_b  = (const float*)d_in[10];
    const float* el_w  = (const float*)d_in[11];
    const float* el_b  = (const float*)d_in[12];
    const float* rl_w  = (const float*)d_in[13];
    const float* rl_b  = (const float*)d_in[14];
    const float* ol_w  = (const float*)d_in[15];
    const float* ol_b  = (const float*)d_in[16];
    const float* ln_g  = (const float*)d_in[17];
    const float* ln_b  = (const float*)d_in[18];
    const float* f1_w  = (const float*)d_in[19];
    const float* f1_b  = (const float*)d_in[20];
    const float* f2_w  = (const float*)d_in[21];
    const float* f2_b  = (const float*)d_in[22];
    const float* f3_w  = (const float*)d_in[23];
    const float* f3_b  = (const float*)d_in[24];
    float* out = (float*)d_out;

    detect_idx_kernel<<<1, 1>>>(ei);
    prep_kernel<<<kE, kH>>>(atom, pos, ew, ei);

    dim3 gQKV(kHH / 128, kE / 128);   // 8 x 32
    k_gemm_Q<<<gQKV, 256>>>(Wq);
    k_gemm_K<<<gQKV, 256>>>(Wk);
    k_gemm_V<<<gQKV, 256>>>(Wv);

    dim3 gH(kH / 128, kE / 128);      // 1 x 32
    k_gemm_hi<<<gH, 256>>>(li_w, li_b);
    k_gemm_hj<<<gH, 256>>>(lj_w, lj_b);

    edgeij_kernel<<<kE, kH>>>();

    // logits = scale * Q @ K^T  (tensor cores via mma.sync, split-bf16)
    k_mma_logits<<<dim3(kE / 128, kE / 128), 256>>>();

    softmax_kernel<<<kE, 256>>>();    // writes split-bf16 P

    // feats = V + el_b + rl_b + edge_ij@el_w + rbf@rl_w  (in g_V)
    feats_bias_kernel<<<(kE * kHH) / 256, 256>>>(el_b, rl_b);
    k_gemm_el<<<gQKV, 256>>>(el_w);
    k_gemm_rl<<<gQKV, 256>>>(rl_w);

    // feats -> FT hi/lo (K-major B operand for pf)
    k_transpose_split_F<<<dim3(kHH / 32, kE / 32), dim3(32, 8)>>>();

    // pf = P @ feats  (tensor cores via mma.sync, split-bf16)
    k_mma_pf<<<dim3(kHH / 128, kE / 128), 256>>>();

    // msg = pf @ ol_w + ol_b
    k_gemm_msg<<<gH, 256>>>(ol_w, ol_b);

    zero_agg_kernel<<<(kN * kH) / 256, 256>>>();
    scatter_kernel<<<kE, kH>>>();

    k_ln_agg<<<kN, kH>>>(ln_g, ln_b);

    dim3 gF(kH / 128, kN / 128);      // 1 x 4
    k_gemm_f1<<<gF, 256>>>(f1_w, f1_b);
    k_gemm_f2<<<gF, 256>>>(f2_w, f2_b);
    k_gemm_f3<<<gF, 256>>>(f3_w, f3_b);

    k_ln_out<<<kN, kH>>>(out, ln_g, ln_b);
}

// round 15
// speedup vs baseline: 1.9725x; 1.2490x over previous
#include <cuda_runtime.h>
#include <cuda_bf16.h>
#include <math.h>
#include <stdint.h>

// Problem constants
constexpr int kN   = 512;    // atoms
constexpr int kE   = 4096;   // edges
constexpr int kH   = 128;    // hidden
constexpr int kHH  = 1024;   // H * NH
constexpr int kRBF = 64;
constexpr int k3H  = 3 * kH; // 384

// ---------------------------------------------------------------------------
// Scratch (device globals; referenced ONLY from device code)
// ---------------------------------------------------------------------------
__device__ int   g_is64;
__device__ int   g_src[kE], g_tgt[kE];
__device__ __align__(16) float g_ai[kE * kH];
__device__ __align__(16) float g_aj[kE * kH];
__device__ __align__(16) float g_hi[kE * kH];
__device__ __align__(16) float g_hj[kE * kH];
__device__ __align__(16) float g_edgeij[kE * k3H];
__device__ __align__(16) float g_rbf[kE * kRBF];
__device__ __align__(16) float g_V[kE * kHH];             // becomes feats
__device__ __align__(16) float g_logits[(size_t)kE * kE];
__device__ __align__(16) float g_msg[kE * kH];
__device__ __align__(16) float g_agg[kN * kH];
__device__ __align__(16) float g_ln0[kN * kH];
__device__ __align__(16) float g_t1[kN * kH];
__device__ __align__(16) float g_t2[kN * kH];
__device__ __align__(16) float g_t3[kN * kH];

// split-bf16 operands
__device__ __align__(16) __nv_bfloat16 g_aihi[kE * kH],  g_ailo[kE * kH];
__device__ __align__(16) __nv_bfloat16 g_ejhi[kE * k3H], g_ejlo[kE * k3H];
__device__ __align__(16) __nv_bfloat16 g_rbfhi[kE * kRBF], g_rbflo[kE * kRBF];
__device__ __align__(16) __nv_bfloat16 g_WThi[k3H * kHH], g_WTlo[k3H * kHH]; // reused
__device__ __align__(16) __nv_bfloat16 g_Qhi[kE * kHH],  g_Qlo[kE * kHH];    // Q, later pf
__device__ __align__(16) __nv_bfloat16 g_Khi[kE * kHH],  g_Klo[kE * kHH];
__device__ __align__(16) __nv_bfloat16 g_Phi[(size_t)kE * kE];
__device__ __align__(16) __nv_bfloat16 g_Plo[(size_t)kE * kE];
__device__ __align__(16) __nv_bfloat16 g_FThi[(size_t)kHH * kE];
__device__ __align__(16) __nv_bfloat16 g_FTlo[(size_t)kHH * kE];

// ---------------------------------------------------------------------------
// Helpers
// ---------------------------------------------------------------------------
__device__ __forceinline__ float softplus_f(float x) {
    return fmaxf(x, 0.0f) + log1pf(expf(-fabsf(x)));
}
__device__ __forceinline__ void split2(float v, __nv_bfloat16& hi, __nv_bfloat16& lo) {
    hi = __float2bfloat16(v);
    lo = __float2bfloat16(v - __bfloat162float(hi));
}
__device__ __forceinline__ uint32_t smem_u32(const void* p) {
    uint32_t a;
    asm("{ .reg .u64 t; cvta.to.shared.u64 t, %1; cvt.u32.u64 %0, t; }"
        : "=r"(a) : "l"(p));
    return a;
}
__device__ __forceinline__ void ldm_x4(uint32_t* r, uint32_t a) {
    asm volatile("ldmatrix.sync.aligned.m8n8.x4.shared.b16 {%0,%1,%2,%3}, [%4];"
                 : "=r"(r[0]), "=r"(r[1]), "=r"(r[2]), "=r"(r[3]) : "r"(a));
}
__device__ __forceinline__ void ldm_x2(uint32_t* r, uint32_t a) {
    asm volatile("ldmatrix.sync.aligned.m8n8.x2.shared.b16 {%0,%1}, [%2];"
                 : "=r"(r[0]), "=r"(r[1]) : "r"(a));
}
__device__ __forceinline__ void mma16816(float* d, const uint32_t* a, const uint32_t* b) {
    asm volatile(
        "mma.sync.aligned.m16n8k16.row.col.f32.bf16.bf16.f32 "
        "{%0,%1,%2,%3}, {%4,%5,%6,%7}, {%8,%9}, {%0,%1,%2,%3};"
        : "+f"(d[0]), "+f"(d[1]), "+f"(d[2]), "+f"(d[3])
        : "r"(a[0]), "r"(a[1]), "r"(a[2]), "r"(a[3]), "r"(b[0]), "r"(b[1]));
}
__device__ __forceinline__ void cp16(void* sdst, const void* gsrc) {
    asm volatile("cp.async.cg.shared.global [%0], [%1], 16;"
                 :: "r"(smem_u32(sdst)), "l"(gsrc));
}
__device__ __forceinline__ void cp_commit() {
    asm volatile("cp.async.commit_group;");
}
template <int Ng>
__device__ __forceinline__ void cp_wait() {
    asm volatile("cp.async.wait_group %0;" :: "n"(Ng));
}

// ---------------------------------------------------------------------------
// Split-bf16 tensor-core GEMM: out = alpha * sum_k A[m][k]*B[n][k] (+C)(+bias)
// A,B (hi,lo) bf16 K-major. CTA 128x128, 256 threads, BK=32, 2-stage cp.async
// pipeline, warp grid 2x4. 3 MMAs per tile (hi*hi + lo*hi + hi*lo).
// Dynamic SMEM: 2 stages * 4 arrays * 128 rows * 40 bf16 (80B pitch) = 80 KB.
// ---------------------------------------------------------------------------
constexpr int SPITCH = 40;                       // bf16 per row (32 + 8 pad)
constexpr int ARR_B  = 128 * SPITCH * 2;         // 10240 B per array
constexpr int STG_B  = 4 * ARR_B;                // 40960 B per stage
constexpr int MMA_SMEM = 2 * STG_B;              // 81920 B

__device__ __forceinline__ void mma_load_stage(
    char* dsm, int s,
    const __nv_bfloat16* __restrict__ Ahi, const __nv_bfloat16* __restrict__ Alo,
    const __nv_bfloat16* __restrict__ Bhi, const __nv_bfloat16* __restrict__ Blo,
    int m0, int n0, int Kd, int k0, int tid)
{
    __nv_bfloat16* dAh = (__nv_bfloat16*)(dsm + s * STG_B);
    __nv_bfloat16* dAl = (__nv_bfloat16*)(dsm + s * STG_B + ARR_B);
    __nv_bfloat16* dBh = (__nv_bfloat16*)(dsm + s * STG_B + 2 * ARR_B);
    __nv_bfloat16* dBl = (__nv_bfloat16*)(dsm + s * STG_B + 3 * ARR_B);
    #pragma unroll
    for (int i = 0; i < 2; i++) {
        int idx = tid + i * 256;                 // 0..511
        int row = idx >> 2, q = idx & 3;         // 4 x 16B per 64B row
        size_t ga = (size_t)(m0 + row) * Kd + k0 + q * 8;
        size_t gb = (size_t)(n0 + row) * Kd + k0 + q * 8;
        cp16(&dAh[row * SPITCH + q * 8], Ahi + ga);
        cp16(&dAl[row * SPITCH + q * 8], Alo + ga);
        cp16(&dBh[row * SPITCH + q * 8], Bhi + gb);
        cp16(&dBl[row * SPITCH + q * 8], Blo + gb);
    }
}

template <int SPLITOUT>
__device__ __forceinline__ void mma_body(
    const __nv_bfloat16* __restrict__ Ahi, const __nv_bfloat16* __restrict__ Alo,
    const __nv_bfloat16* __restrict__ Bhi, const __nv_bfloat16* __restrict__ Blo,
    float* __restrict__ C, __nv_bfloat16* __restrict__ Chi,
    __nv_bfloat16* __restrict__ Clo, int Kd, int ldC, float alpha,
    const float* __restrict__ bias, int accum)
{
    extern __shared__ __align__(16) char dsm[];
    int tid = threadIdx.x;
    int wid = tid >> 5, lane = tid & 31;
    int wm = wid & 1, wn = wid >> 1;             // 2 x 4 warp grid
    int m0 = blockIdx.y * 128, n0 = blockIdx.x * 128;

    float acc[4][4][4] = {};
    int nCh = Kd >> 5;

    mma_load_stage(dsm, 0, Ahi, Alo, Bhi, Blo, m0, n0, Kd, 0, tid);
    cp_commit();

    for (int c = 0; c < nCh; c++) {
        int s = c & 1;
        if (c + 1 < nCh) {
            mma_load_stage(dsm, s ^ 1, Ahi, Alo, Bhi, Blo, m0, n0, Kd,
                           (c + 1) << 5, tid);
            cp_commit();
            cp_wait<1>();
        } else {
            cp_wait<0>();
        }
        __syncthreads();

        __nv_bfloat16* sAh = (__nv_bfloat16*)(dsm + s * STG_B);
        __nv_bfloat16* sAl = (__nv_bfloat16*)(dsm + s * STG_B + ARR_B);
        __nv_bfloat16* sBh = (__nv_bfloat16*)(dsm + s * STG_B + 2 * ARR_B);
        __nv_bfloat16* sBl = (__nv_bfloat16*)(dsm + s * STG_B + 3 * ARR_B);

        #pragma unroll
        for (int ks = 0; ks < 2; ks++) {
            uint32_t ahi[4][4], alo[4][4];
            #pragma unroll
            for (int mt = 0; mt < 4; mt++) {
                int r  = wm * 64 + mt * 16 + (lane & 15);
                int cb = ks * 16 + (lane >> 4) * 8;
                ldm_x4(ahi[mt], smem_u32(&sAh[r * SPITCH + cb]));
                ldm_x4(alo[mt], smem_u32(&sAl[r * SPITCH + cb]));
            }
            uint32_t bhi[4][2], blo[4][2];
            #pragma unroll
            for (int nt = 0; nt < 4; nt++) {
                int r  = wn * 32 + nt * 8 + (lane & 7);
                int cb = ks * 16 + ((lane >> 3) & 1) * 8;
                ldm_x2(bhi[nt], smem_u32(&sBh[r * SPITCH + cb]));
                ldm_x2(blo[nt], smem_u32(&sBl[r * SPITCH + cb]));
            }
            #pragma unroll
            for (int mt = 0; mt < 4; mt++)
                #pragma unroll
                for (int nt = 0; nt < 4; nt++) {
                    mma16816(acc[mt][nt], ahi[mt], bhi[nt]);
                    mma16816(acc[mt][nt], alo[mt], bhi[nt]);
                    mma16816(acc[mt][nt], ahi[mt], blo[nt]);
                }
        }
        __syncthreads();
    }

    // Epilogue
    int gr = lane >> 2, gc = (lane & 3) * 2;
    #pragma unroll
    for (int mt = 0; mt < 4; mt++) {
        int row = m0 + wm * 64 + mt * 16 + gr;
        #pragma unroll
        for (int nt = 0; nt < 4; nt++) {
            int col = n0 + wn * 32 + nt * 8 + gc;
            #pragma unroll
            for (int h = 0; h < 2; h++) {        // h=0: row, h=1: row+8
                int r = row + h * 8;
                float v0 = alpha * acc[mt][nt][h * 2 + 0];
                float v1 = alpha * acc[mt][nt][h * 2 + 1];
                if (bias)  { v0 += bias[col]; v1 += bias[col + 1]; }
                if (accum) {
                    float2 old = *reinterpret_cast<float2*>(
                        C + (size_t)r * ldC + col);
                    v0 += old.x; v1 += old.y;
                }
                if (SPLITOUT) {
                    __nv_bfloat162 h2, l2;
                    split2(v0, h2.x, l2.x);
                    split2(v1, h2.y, l2.y);
                    *reinterpret_cast<__nv_bfloat162*>(
                        Chi + (size_t)r * ldC + col) = h2;
                    *reinterpret_cast<__nv_bfloat162*>(
                        Clo + (size_t)r * ldC + col) = l2;
                } else {
                    *reinterpret_cast<float2*>(C + (size_t)r * ldC + col) =
                        make_float2(v0, v1);
                }
            }
        }
    }
}

// ---- mma wrappers ---------------------------------------------------------
__global__ void __launch_bounds__(256) k_mma_Q() {
    mma_body<1>(g_aihi, g_ailo, g_WThi, g_WTlo, nullptr, g_Qhi, g_Qlo,
                kH, kHH, 1.0f, nullptr, 0);
}
__global__ void __launch_bounds__(256) k_mma_K() {
    mma_body<1>(g_aihi, g_ailo, g_WThi, g_WTlo, nullptr, g_Khi, g_Klo,
                kH, kHH, 1.0f, nullptr, 0);
}
__global__ void __launch_bounds__(256) k_mma_V() {
    mma_body<0>(g_aihi, g_ailo, g_WThi, g_WTlo, g_V, nullptr, nullptr,
                kH, kHH, 1.0f, nullptr, 0);
}
__global__ void __launch_bounds__(256) k_mma_el() {
    mma_body<0>(g_ejhi, g_ejlo, g_WThi, g_WTlo, g_V, nullptr, nullptr,
                k3H, kHH, 1.0f, nullptr, 1);
}
__global__ void __launch_bounds__(256) k_mma_rl() {
    mma_body<0>(g_rbfhi, g_rbflo, g_WThi, g_WTlo, g_V, nullptr, nullptr,
                kRBF, kHH, 1.0f, nullptr, 1);
}
__global__ void __launch_bounds__(256) k_mma_logits() {
    mma_body<0>(g_Qhi, g_Qlo, g_Khi, g_Klo, g_logits, nullptr, nullptr,
                kHH, kE, 0.08838834764831845f, nullptr, 0);
}
__global__ void __launch_bounds__(256) k_mma_pf() {
    // pf split written into dead Q buffers
    mma_body<1>(g_Phi, g_Plo, g_FThi, g_FTlo, nullptr, g_Qhi, g_Qlo,
                kE, kHH, 1.0f, nullptr, 0);
}
__global__ void __launch_bounds__(256) k_mma_msg(const float* __restrict__ b) {
    mma_body<0>(g_Qhi, g_Qlo, g_WThi, g_WTlo, g_msg, nullptr, nullptr,
                kHH, kH, 1.0f, b, 0);
}

// ---------------------------------------------------------------------------
// Split kernels: fp32 -> bf16 (hi, lo)
// ---------------------------------------------------------------------------
__global__ void k_split_ai() {
    int i = blockIdx.x * 256 + threadIdx.x;
    split2(g_ai[i], g_aihi[i], g_ailo[i]);
}
__global__ void k_split_ej() {
    int i = blockIdx.x * 256 + threadIdx.x;
    split2(g_edgeij[i], g_ejhi[i], g_ejlo[i]);
}
__global__ void k_split_rbf() {
    int i = blockIdx.x * 256 + threadIdx.x;
    split2(g_rbf[i], g_rbfhi[i], g_rbflo[i]);
}

// Weight transpose+split: W [R x C] fp32 row-major -> g_WT [C x R] bf16 hi/lo
template <int R, int C>
__global__ void k_tsplitW(const float* __restrict__ W) {
    __shared__ float tile[32][33];
    int tx = threadIdx.x, ty = threadIdx.y;      // 32 x 8
    int c0 = blockIdx.x * 32;
    int r0 = blockIdx.y * 32;
    #pragma unroll
    for (int i = 0; i < 4; i++)
        tile[ty + i * 8][tx] = W[(size_t)(r0 + ty + i * 8) * C + c0 + tx];
    __syncthreads();
    #pragma unroll
    for (int i = 0; i < 4; i++) {
        int c = c0 + ty + i * 8;
        int r = r0 + tx;
        float v = tile[tx][ty + i * 8];
        __nv_bfloat16 h, l;
        split2(v, h, l);
        g_WThi[(size_t)c * R + r] = h;
        g_WTlo[(size_t)c * R + r] = l;
    }
}

// ---------------------------------------------------------------------------
// Detect edge_indices element width (int64 vs int32).
// ---------------------------------------------------------------------------
__global__ void detect_idx_kernel(const void* __restrict__ ei) {
    const int* p = (const int*)ei;
    int looks64 = 1;
    for (int i = 0; i < 32; i++)
        if (p[2 * i + 1] != 0) looks64 = 0;
    g_is64 = looks64;
}

// ---------------------------------------------------------------------------
// prep: ai/aj = atom[tgt/src] + ew ; rbf features.  grid kE x kH
// ---------------------------------------------------------------------------
__global__ void prep_kernel(const float* __restrict__ atom,
                            const float* __restrict__ pos,
                            const float* __restrict__ ew,
                            const void* __restrict__ ei) {
    int e = blockIdx.x, t = threadIdx.x;
    __shared__ float sdist;
    __shared__ int ssrc, stgt;
    if (t == 0) {
        int s, g;
        if (g_is64) {
            const long long* p = (const long long*)ei;
            s = (int)p[e];  g = (int)p[kE + e];
        } else {
            const int* p = (const int*)ei;
            s = p[e];  g = p[kE + e];
        }
        ssrc = s; stgt = g;
        g_src[e] = s; g_tgt[e] = g;
        float dx = pos[g * 3 + 0] - pos[s * 3 + 0];
        float dy = pos[g * 3 + 1] - pos[s * 3 + 1];
        float dz = pos[g * 3 + 2] - pos[s * 3 + 2];
        sdist = sqrtf(dx * dx + dy * dy + dz * dz);
    }
    __syncthreads();
    float w = ew[e];
    g_ai[e * kH + t] = atom[stgt * kH + t] + w;
    g_aj[e * kH + t] = atom[ssrc * kH + t] + w;
    if (t < kRBF) {
        float d  = sdist;
        float x  = d * 0.1f;
        float x3 = x * x * x, x4 = x3 * x, x5 = x4 * x;
        float cut = (x < 1.0f) ? (1.0f - 6.0f * x5 + 15.0f * x4 - 10.0f * x3) : 0.0f;
        float em10 = expf(-10.0f);
        float step = (em10 - 1.0f) / 63.0f;
        float center = 1.0f + (float)t * step;
        float wd = 0.5f / ((1.0f - em10) / 64.0f);
        wd = wd * wd;
        float diff = expf(-d) - center;
        g_rbf[e * kRBF + t] = cut * expf(-wd * diff * diff);
    }
}

// edge_ij = [hi+hj, hi-hj, hi*hj]   grid: kE x kH
__global__ void edgeij_kernel() {
    int e = blockIdx.x, t = threadIdx.x;
    float hi = g_hi[e * kH + t];
    float hj = g_hj[e * kH + t];
    size_t b = (size_t)e * k3H;
    g_edgeij[b + t]          = hi + hj;
    g_edgeij[b + kH + t]     = hi - hj;
    g_edgeij[b + 2 * kH + t] = hi * hj;
}

// ---------------------------------------------------------------------------
// FFMA GEMM body (small GEMMs: hi, hj, f1-3)
// ---------------------------------------------------------------------------
template <int ACT>
__device__ __forceinline__
void gemm_body(const float* __restrict__ A, const float* __restrict__ B,
               float* __restrict__ C, int M, int Nd, int Kd,
               const float* __restrict__ bias) {
    constexpr int BM = 128, BN = 128, BK = 16;
    __shared__ __align__(16) float As[BK][BM + 4];
    __shared__ __align__(16) float Bs[BK][BN + 4];
    int tid = threadIdx.x;
    int tx = tid & 15, ty = tid >> 4;
    int m0 = blockIdx.y * BM, n0 = blockIdx.x * BN;
    float acc[8][8] = {};

    for (int k0 = 0; k0 < Kd; k0 += BK) {
        #pragma unroll
        for (int i = 0; i < 2; i++) {
            int f = tid + i * 256;
            int row = f >> 2, c4 = (f & 3) * 4;
            float4 av = *reinterpret_cast<const float4*>(
                &A[(size_t)(m0 + row) * Kd + k0 + c4]);
            As[c4 + 0][row] = av.x; As[c4 + 1][row] = av.y;
            As[c4 + 2][row] = av.z; As[c4 + 3][row] = av.w;
        }
        #pragma unroll
        for (int i = 0; i < 2; i++) {
            int f = tid + i * 256;
            int row = f >> 5, c4 = (f & 31) * 4;
            float4 bv = *reinterpret_cast<const float4*>(
                &B[(size_t)(k0 + row) * Nd + n0 + c4]);
            *reinterpret_cast<float4*>(&Bs[row][c4]) = bv;
        }
        __syncthreads();
        #pragma unroll
        for (int k = 0; k < BK; k++) {
            float4 a0 = *reinterpret_cast<const float4*>(&As[k][ty * 8]);
            float4 a1 = *reinterpret_cast<const float4*>(&As[k][ty * 8 + 4]);
            float4 b0 = *reinterpret_cast<const float4*>(&Bs[k][tx * 8]);
            float4 b1 = *reinterpret_cast<const float4*>(&Bs[k][tx * 8 + 4]);
            float a[8] = {a0.x, a0.y, a0.z, a0.w, a1.x, a1.y, a1.z, a1.w};
            float b[8] = {b0.x, b0.y, b0.z, b0.w, b1.x, b1.y, b1.z, b1.w};
            #pragma unroll
            for (int i = 0; i < 8; i++)
                #pragma unroll
                for (int j = 0; j < 8; j++)
                    acc[i][j] = fmaf(a[i], b[j], acc[i][j]);
        }
        __syncthreads();
    }

    #pragma unroll
    for (int i = 0; i < 8; i++) {
        int m = m0 + ty * 8 + i;
        #pragma unroll
        for (int j = 0; j < 8; j++) {
            int n = n0 + tx * 8 + j;
            float v = acc[i][j];
            if (bias) v += bias[n];
            if (ACT)  v = softplus_f(v);
            C[(size_t)m * Nd + n] = v;
        }
    }
}

__global__ __launch_bounds__(256) void k_gemm_hi(const float* __restrict__ W,
                                                 const float* __restrict__ b) {
    gemm_body<0>(g_ai, W, g_hi, kE, kH, kH, b);
}
__global__ __launch_bounds__(256) void k_gemm_hj(const float* __restrict__ W,
                                                 const float* __restrict__ b) {
    gemm_body<0>(g_aj, W, g_hj, kE, kH, kH, b);
}
__global__ __launch_bounds__(256) void k_gemm_f1(const float* __restrict__ W,
                                                 const float* __restrict__ b) {
    gemm_body<1>(g_ln0, W, g_t1, kN, kH, kH, b);
}
__global__ __launch_bounds__(256) void k_gemm_f2(const float* __restrict__ W,
                                                 const float* __restrict__ b) {
    gemm_body<1>(g_t1, W, g_t2, kN, kH, kH, b);
}
__global__ __launch_bounds__(256) void k_gemm_f3(const float* __restrict__ W,
                                                 const float* __restrict__ b) {
    gemm_body<1>(g_t2, W, g_t3, kN, kH, kH, b);
}

// ---------------------------------------------------------------------------
// Per-row segmented softmax over columns, groups = src[col].
// Pass 3 writes split-bf16 P directly. grid: kE x 256
// ---------------------------------------------------------------------------
__global__ void softmax_kernel() {
    __shared__ unsigned int smax[kN];
    __shared__ float ssum[kN];
    __shared__ int ssrc[kE];
    const int T = 256;
    int row = blockIdx.x, t = threadIdx.x;
    for (int i = t; i < kN; i += T) { smax[i] = 0u; ssum[i] = 0.0f; }
    for (int i = t; i < kE; i += T) ssrc[i] = g_src[i];
    __syncthreads();
    const float* L = g_logits + (size_t)row * kE;
    for (int b = t; b < kE; b += T) {
        unsigned u = __float_as_uint(L[b]);
        u = (u & 0x80000000u) ? ~u : (u | 0x80000000u);
        atomicMax(&smax[ssrc[b]], u);
    }
    __syncthreads();
    for (int b = t; b < kE; b += T) {
        unsigned u = smax[ssrc[b]];
        float m = (u & 0x80000000u) ? __uint_as_float(u & 0x7FFFFFFFu)
                                    : __uint_as_float(~u);
        atomicAdd(&ssum[ssrc[b]], __expf(L[b] - m));
    }
    __syncthreads();
    for (int b = t; b < kE; b += T) {
        int s = ssrc[b];
        unsigned u = smax[s];
        float m = (u & 0x80000000u) ? __uint_as_float(u & 0x7FFFFFFFu)
                                    : __uint_as_float(~u);
        float p = __expf(L[b] - m) / ssum[s];
        __nv_bfloat16 h, l;
        split2(p, h, l);
        g_Phi[(size_t)row * kE + b] = h;
        g_Plo[(size_t)row * kE + b] = l;
    }
}

// feats init: V += el_b + rl_b (broadcast over columns)
__global__ void feats_bias_kernel(const float* __restrict__ el_b,
                                  const float* __restrict__ rl_b) {
    int i = blockIdx.x * blockDim.x + threadIdx.x;
    int c = i & (kHH - 1);
    g_V[i] += el_b[c] + rl_b[c];
}

// F [kE x kHH] float -> FT hi/lo [kHH x kE] bf16 (tiled transpose + split)
__global__ void k_transpose_split_F() {
    __shared__ float tile[32][33];
    int tx = threadIdx.x, ty = threadIdx.y;   // 32 x 8
    int n0 = blockIdx.x * 32;
    int k0 = blockIdx.y * 32;
    #pragma unroll
    for (int i = 0; i < 4; i++)
        tile[ty + i * 8][tx] = g_V[(size_t)(k0 + ty + i * 8) * kHH + n0 + tx];
    __syncthreads();
    #pragma unroll
    for (int i = 0; i < 4; i++) {
        int n = n0 + ty + i * 8;
        int k = k0 + tx;
        float v = tile[tx][ty + i * 8];
        __nv_bfloat16 h, l;
        split2(v, h, l);
        g_FThi[(size_t)n * kE + k] = h;
        g_FTlo[(size_t)n * kE + k] = l;
    }
}

__global__ void zero_agg_kernel() {
    int i = blockIdx.x * blockDim.x + threadIdx.x;
    g_agg[i] = 0.0f;
}

// segment_sum(msg, tgt) via atomics. grid kE x kH
__global__ void scatter_kernel() {
    int e = blockIdx.x, t = threadIdx.x;
    atomicAdd(&g_agg[g_tgt[e] * kH + t], g_msg[e * kH + t]);
}

// ---------------------------------------------------------------------------
// LayerNorm over H=128, one block (128 threads) per node.
// ---------------------------------------------------------------------------
__device__ __forceinline__ float blockSum128(float v) {
    __shared__ float sw[4];
    __syncthreads();
    int lane = threadIdx.x & 31, wid = threadIdx.x >> 5;
    #pragma unroll
    for (int o = 16; o; o >>= 1) v += __shfl_down_sync(0xffffffffu, v, o);
    if (lane == 0) sw[wid] = v;
    __syncthreads();
    if (threadIdx.x == 0) sw[0] = sw[0] + sw[1] + sw[2] + sw[3];
    __syncthreads();
    return sw[0];
}

__device__ __forceinline__ void ln_body(const float* __restrict__ in,
                                        float* __restrict__ out,
                                        const float* __restrict__ gw,
                                        const float* __restrict__ gb) {
    int n = blockIdx.x, t = threadIdx.x;
    float x = in[n * kH + t];
    float mu = blockSum128(x) * (1.0f / kH);
    float d = x - mu;
    float var = blockSum128(d * d) * (1.0f / kH);
    out[n * kH + t] = d * rsqrtf(var + 1e-5f) * gw[t] + gb[t];
}

__global__ void k_ln_agg(const float* __restrict__ gw, const float* __restrict__ gb) {
    ln_body(g_agg, g_ln0, gw, gb);
}
__global__ void k_ln_out(float* __restrict__ out,
                         const float* __restrict__ gw, const float* __restrict__ gb) {
    ln_body(g_t3, out, gw, gb);
}

// ---------------------------------------------------------------------------
// Launch
// ---------------------------------------------------------------------------
extern "C" void kernel_launch(void* const* d_in, const int* in_sizes, int n_in,
                              void* d_out, int out_size) {
    const float* atom  = (const float*)d_in[0];
    const float* pos   = (const float*)d_in[1];
    const float* ew    = (const float*)d_in[2];
    const void*  ei    = d_in[3];
    const float* Wq    = (const float*)d_in[4];
    const float* Wk    = (const float*)d_in[5];
    const float* Wv    = (const float*)d_in[6];
    const float* li_w  = (const float*)d_in[7];
    const float* li_b  = (const float*)d_in[8];
    const float* lj_w  = (const float*)d_in[9];
    const float* lj_b  = (const float*)d_in[10];
    const float* el_w  = (const float*)d_in[11];
    const float* el_b  = (const float*)d_in[12];
    const float* rl_w  = (const float*)d_in[13];
    const float* rl_b  = (const float*)d_in[14];
    const float* ol_w  = (const float*)d_in[15];
    const float* ol_b  = (const float*)d_in[16];
    const float* ln_g  = (const float*)d_in[17];
    const float* ln_b  = (const float*)d_in[18];
    const float* f1_w  = (const float*)d_in[19];
    const float* f1_b  = (const float*)d_in[20];
    const float* f2_w  = (const float*)d_in[21];
    const float* f2_b  = (const float*)d_in[22];
    const float* f3_w  = (const float*)d_in[23];
    const float* f3_b  = (const float*)d_in[24];
    float* out = (float*)d_out;

    // Idempotent, capture-legal; called unconditionally every invocation
    // (no static guards per harness contract).
    cudaFuncSetAttribute(k_mma_Q,      cudaFuncAttributeMaxDynamicSharedMemorySize, MMA_SMEM);
    cudaFuncSetAttribute(k_mma_K,      cudaFuncAttributeMaxDynamicSharedMemorySize, MMA_SMEM);
    cudaFuncSetAttribute(k_mma_V,      cudaFuncAttributeMaxDynamicSharedMemorySize, MMA_SMEM);
    cudaFuncSetAttribute(k_mma_el,     cudaFuncAttributeMaxDynamicSharedMemorySize, MMA_SMEM);
    cudaFuncSetAttribute(k_mma_rl,     cudaFuncAttributeMaxDynamicSharedMemorySize, MMA_SMEM);
    cudaFuncSetAttribute(k_mma_logits, cudaFuncAttributeMaxDynamicSharedMemorySize, MMA_SMEM);
    cudaFuncSetAttribute(k_mma_pf,     cudaFuncAttributeMaxDynamicSharedMemorySize, MMA_SMEM);
    cudaFuncSetAttribute(k_mma_msg,    cudaFuncAttributeMaxDynamicSharedMemorySize, MMA_SMEM);

    detect_idx_kernel<<<1, 1>>>(ei);
    prep_kernel<<<kE, kH>>>(atom, pos, ew, ei);

    // QKV via tensor cores (split ai once; weights transposed+split in turn)
    k_split_ai<<<(kE * kH) / 256, 256>>>();
    dim3 gQKV(kHH / 128, kE / 128);   // 8 x 32
    k_tsplitW<kH, kHH><<<dim3(kHH / 32, kH / 32), dim3(32, 8)>>>(Wq);
    k_mma_Q<<<gQKV, 256, MMA_SMEM>>>();
    k_tsplitW<kH, kHH><<<dim3(kHH / 32, kH / 32), dim3(32, 8)>>>(Wk);
    k_mma_K<<<gQKV, 256, MMA_SMEM>>>();
    k_tsplitW<kH, kHH><<<dim3(kHH / 32, kH / 32), dim3(32, 8)>>>(Wv);
    k_mma_V<<<gQKV, 256, MMA_SMEM>>>();

    dim3 gH(kH / 128, kE / 128);      // 1 x 32
    k_gemm_hi<<<gH, 256>>>(li_w, li_b);
    k_gemm_hj<<<gH, 256>>>(lj_w, lj_b);
    edgeij_kernel<<<kE, kH>>>();

    // logits = scale * Q @ K^T  (pipelined split-bf16 mma)
    k_mma_logits<<<dim3(kE / 128, kE / 128), 256, MMA_SMEM>>>();

    softmax_kernel<<<kE, 256>>>();    // writes split-bf16 P

    // feats = V + el_b + rl_b + edge_ij@el_w + rbf@rl_w   (in g_V)
    feats_bias_kernel<<<(kE * kHH) / 256, 256>>>(el_b, rl_b);
    k_split_ej<<<(kE * k3H) / 256, 256>>>();
    k_tsplitW<k3H, kHH><<<dim3(kHH / 32, k3H / 32), dim3(32, 8)>>>(el_w);
    k_mma_el<<<gQKV, 256, MMA_SMEM>>>();
    k_split_rbf<<<(kE * kRBF) / 256, 256>>>();
    k_tsplitW<kRBF, kHH><<<dim3(kHH / 32, kRBF / 32), dim3(32, 8)>>>(rl_w);
    k_mma_rl<<<gQKV, 256, MMA_SMEM>>>();

    // feats -> FT hi/lo (K-major B operand for pf)
    k_transpose_split_F<<<dim3(kHH / 32, kE / 32), dim3(32, 8)>>>();

    // pf = P @ feats  (split result into dead Q buffers)
    k_mma_pf<<<gQKV, 256, MMA_SMEM>>>();

    // msg = pf @ ol_w + ol_b
    k_tsplitW<kHH, kH><<<dim3(kH / 32, kHH / 32), dim3(32, 8)>>>(ol_w);
    k_mma_msg<<<dim3(kH / 128, kE / 128), 256, MMA_SMEM>>>(ol_b);

    zero_agg_kernel<<<(kN * kH) / 256, 256>>>();
    scatter_kernel<<<kE, kH>>>();

    k_ln_agg<<<kN, kH>>>(ln_g, ln_b);

    dim3 gF(kH / 128, kN / 128);      // 1 x 4
    k_gemm_f1<<<gF, 256>>>(f1_w, f1_b);
    k_gemm_f2<<<gF, 256>>>(f2_w, f2_b);
    k_gemm_f3<<<gF, 256>>>(f3_w, f3_b);

    k_ln_out<<<kN, kH>>>(out, ln_g, ln_b);
}

// round 16
// speedup vs baseline: 2.7309x; 1.3845x over previous
#include <cuda_runtime.h>
#include <cuda_bf16.h>
#include <math.h>
#include <stdint.h>

// Problem constants
constexpr int kN   = 512;    // atoms
constexpr int kE   = 4096;   // edges
constexpr int kH   = 128;    // hidden
constexpr int kHH  = 1024;   // H * NH
constexpr int kRBF = 64;
constexpr int k3H  = 3 * kH; // 384

// ---------------------------------------------------------------------------
// Scratch (device globals; referenced ONLY from device code)
// ---------------------------------------------------------------------------
__device__ int   g_is64;
__device__ int   g_src[kE], g_tgt[kE];
__device__ __align__(16) float g_ai[kE * kH];
__device__ __align__(16) float g_aj[kE * kH];
__device__ __align__(16) float g_hi[kE * kH];   // hi features; later FW (E x H)
__device__ __align__(16) float g_hj[kE * kH];
__device__ __align__(16) float g_edgeij[kE * k3H];
__device__ __align__(16) float g_rbf[kE * kRBF];
__device__ __align__(16) float g_V[kE * kHH];             // becomes feats
__device__ __align__(16) float g_logits[(size_t)kE * kE];
__device__ __align__(16) float g_msg[kE * kH];
__device__ __align__(16) float g_agg[kN * kH];
__device__ __align__(16) float g_ln0[kN * kH];
__device__ __align__(16) float g_t1[kN * kH];
__device__ __align__(16) float g_t2[kN * kH];
__device__ __align__(16) float g_t3[kN * kH];

// split-bf16 operands
__device__ __align__(16) __nv_bfloat16 g_aihi[kE * kH],  g_ailo[kE * kH];
__device__ __align__(16) __nv_bfloat16 g_ejhi[kE * k3H], g_ejlo[kE * k3H];
__device__ __align__(16) __nv_bfloat16 g_rbfhi[kE * kRBF], g_rbflo[kE * kRBF];
__device__ __align__(16) __nv_bfloat16 g_WThi[k3H * kHH], g_WTlo[k3H * kHH]; // reused
__device__ __align__(16) __nv_bfloat16 g_Qhi[kE * kHH],  g_Qlo[kE * kHH];
__device__ __align__(16) __nv_bfloat16 g_Khi[kE * kHH],  g_Klo[kE * kHH];    // K; later FW^T
__device__ __align__(16) __nv_bfloat16 g_Phi[(size_t)kE * kE];
__device__ __align__(16) __nv_bfloat16 g_Plo[(size_t)kE * kE];
__device__ __align__(16) __nv_bfloat16 g_Fhi[(size_t)kE * kHH];              // feats split
__device__ __align__(16) __nv_bfloat16 g_Flo[(size_t)kE * kHH];

// ---------------------------------------------------------------------------
// Helpers
// ---------------------------------------------------------------------------
__device__ __forceinline__ float softplus_f(float x) {
    return fmaxf(x, 0.0f) + log1pf(expf(-fabsf(x)));
}
__device__ __forceinline__ void split2(float v, __nv_bfloat16& hi, __nv_bfloat16& lo) {
    hi = __float2bfloat16(v);
    lo = __float2bfloat16(v - __bfloat162float(hi));
}
__device__ __forceinline__ uint32_t smem_u32(const void* p) {
    uint32_t a;
    asm("{ .reg .u64 t; cvta.to.shared.u64 t, %1; cvt.u32.u64 %0, t; }"
        : "=r"(a) : "l"(p));
    return a;
}
__device__ __forceinline__ void ldm_x4(uint32_t* r, uint32_t a) {
    asm volatile("ldmatrix.sync.aligned.m8n8.x4.shared.b16 {%0,%1,%2,%3}, [%4];"
                 : "=r"(r[0]), "=r"(r[1]), "=r"(r[2]), "=r"(r[3]) : "r"(a));
}
__device__ __forceinline__ void ldm_x2(uint32_t* r, uint32_t a) {
    asm volatile("ldmatrix.sync.aligned.m8n8.x2.shared.b16 {%0,%1}, [%2];"
                 : "=r"(r[0]), "=r"(r[1]) : "r"(a));
}
__device__ __forceinline__ void mma16816(float* d, const uint32_t* a, const uint32_t* b) {
    asm volatile(
        "mma.sync.aligned.m16n8k16.row.col.f32.bf16.bf16.f32 "
        "{%0,%1,%2,%3}, {%4,%5,%6,%7}, {%8,%9}, {%0,%1,%2,%3};"
        : "+f"(d[0]), "+f"(d[1]), "+f"(d[2]), "+f"(d[3])
        : "r"(a[0]), "r"(a[1]), "r"(a[2]), "r"(a[3]), "r"(b[0]), "r"(b[1]));
}
__device__ __forceinline__ void cp16(void* sdst, const void* gsrc) {
    asm volatile("cp.async.cg.shared.global [%0], [%1], 16;"
                 :: "r"(smem_u32(sdst)), "l"(gsrc));
}
__device__ __forceinline__ void cp_commit() {
    asm volatile("cp.async.commit_group;");
}
template <int Ng>
__device__ __forceinline__ void cp_wait() {
    asm volatile("cp.async.wait_group %0;" :: "n"(Ng));
}

// ---------------------------------------------------------------------------
// Split-bf16 tensor-core GEMM: out(+)= alpha * sum_{k in [kBeg,kEnd)} A[m][k]*B[n][k]
// A,B (hi,lo) bf16 K-major (row stride ldK). CTA 128x128, 256 threads, BK=32,
// 2-stage cp.async pipeline, warp grid 2x4. 3 MMAs/tile (hi*hi+lo*hi+hi*lo).
// ATOMIC=1: atomicAdd into C (K-split across blockIdx.z).
// ---------------------------------------------------------------------------
constexpr int SPITCH = 40;                       // bf16 per row (32 + 8 pad)
constexpr int ARR_B  = 128 * SPITCH * 2;         // 10240 B per array
constexpr int STG_B  = 4 * ARR_B;                // 40960 B per stage
constexpr int MMA_SMEM = 2 * STG_B;              // 81920 B

__device__ __forceinline__ void mma_load_stage(
    char* dsm, int s,
    const __nv_bfloat16* __restrict__ Ahi, const __nv_bfloat16* __restrict__ Alo,
    const __nv_bfloat16* __restrict__ Bhi, const __nv_bfloat16* __restrict__ Blo,
    int m0, int n0, int ldK, int k0, int tid)
{
    __nv_bfloat16* dAh = (__nv_bfloat16*)(dsm + s * STG_B);
    __nv_bfloat16* dAl = (__nv_bfloat16*)(dsm + s * STG_B + ARR_B);
    __nv_bfloat16* dBh = (__nv_bfloat16*)(dsm + s * STG_B + 2 * ARR_B);
    __nv_bfloat16* dBl = (__nv_bfloat16*)(dsm + s * STG_B + 3 * ARR_B);
    #pragma unroll
    for (int i = 0; i < 2; i++) {
        int idx = tid + i * 256;                 // 0..511
        int row = idx >> 2, q = idx & 3;         // 4 x 16B per 64B row
        size_t ga = (size_t)(m0 + row) * ldK + k0 + q * 8;
        size_t gb = (size_t)(n0 + row) * ldK + k0 + q * 8;
        cp16(&dAh[row * SPITCH + q * 8], Ahi + ga);
        cp16(&dAl[row * SPITCH + q * 8], Alo + ga);
        cp16(&dBh[row * SPITCH + q * 8], Bhi + gb);
        cp16(&dBl[row * SPITCH + q * 8], Blo + gb);
    }
}

template <int SPLITOUT, int ATOMIC>
__device__ __forceinline__ void mma_body(
    const __nv_bfloat16* __restrict__ Ahi, const __nv_bfloat16* __restrict__ Alo,
    const __nv_bfloat16* __restrict__ Bhi, const __nv_bfloat16* __restrict__ Blo,
    float* __restrict__ C, __nv_bfloat16* __restrict__ Chi,
    __nv_bfloat16* __restrict__ Clo, int ldK, int kBeg, int kEnd, int ldC,
    float alpha, const float* __restrict__ bias, int accum)
{
    extern __shared__ __align__(16) char dsm[];
    int tid = threadIdx.x;
    int wid = tid >> 5, lane = tid & 31;
    int wm = wid & 1, wn = wid >> 1;             // 2 x 4 warp grid
    int m0 = blockIdx.y * 128, n0 = blockIdx.x * 128;

    float acc[4][4][4] = {};
    int nCh = (kEnd - kBeg) >> 5;

    mma_load_stage(dsm, 0, Ahi, Alo, Bhi, Blo, m0, n0, ldK, kBeg, tid);
    cp_commit();

    for (int c = 0; c < nCh; c++) {
        int s = c & 1;
        if (c + 1 < nCh) {
            mma_load_stage(dsm, s ^ 1, Ahi, Alo, Bhi, Blo, m0, n0, ldK,
                           kBeg + ((c + 1) << 5), tid);
            cp_commit();
            cp_wait<1>();
        } else {
            cp_wait<0>();
        }
        __syncthreads();

        __nv_bfloat16* sAh = (__nv_bfloat16*)(dsm + s * STG_B);
        __nv_bfloat16* sAl = (__nv_bfloat16*)(dsm + s * STG_B + ARR_B);
        __nv_bfloat16* sBh = (__nv_bfloat16*)(dsm + s * STG_B + 2 * ARR_B);
        __nv_bfloat16* sBl = (__nv_bfloat16*)(dsm + s * STG_B + 3 * ARR_B);

        #pragma unroll
        for (int ks = 0; ks < 2; ks++) {
            uint32_t ahi[4][4], alo[4][4];
            #pragma unroll
            for (int mt = 0; mt < 4; mt++) {
                int r  = wm * 64 + mt * 16 + (lane & 15);
                int cb = ks * 16 + (lane >> 4) * 8;
                ldm_x4(ahi[mt], smem_u32(&sAh[r * SPITCH + cb]));
                ldm_x4(alo[mt], smem_u32(&sAl[r * SPITCH + cb]));
            }
            uint32_t bhi[4][2], blo[4][2];
            #pragma unroll
            for (int nt = 0; nt < 4; nt++) {
                int r  = wn * 32 + nt * 8 + (lane & 7);
                int cb = ks * 16 + ((lane >> 3) & 1) * 8;
                ldm_x2(bhi[nt], smem_u32(&sBh[r * SPITCH + cb]));
                ldm_x2(blo[nt], smem_u32(&sBl[r * SPITCH + cb]));
            }
            #pragma unroll
            for (int mt = 0; mt < 4; mt++)
                #pragma unroll
                for (int nt = 0; nt < 4; nt++) {
                    mma16816(acc[mt][nt], ahi[mt], bhi[nt]);
                    mma16816(acc[mt][nt], alo[mt], bhi[nt]);
                    mma16816(acc[mt][nt], ahi[mt], blo[nt]);
                }
        }
        __syncthreads();
    }

    // Epilogue
    int gr = lane >> 2, gc = (lane & 3) * 2;
    #pragma unroll
    for (int mt = 0; mt < 4; mt++) {
        int row = m0 + wm * 64 + mt * 16 + gr;
        #pragma unroll
        for (int nt = 0; nt < 4; nt++) {
            int col = n0 + wn * 32 + nt * 8 + gc;
            #pragma unroll
            for (int h = 0; h < 2; h++) {        // h=0: row, h=1: row+8
                int r = row + h * 8;
                float v0 = alpha * acc[mt][nt][h * 2 + 0];
                float v1 = alpha * acc[mt][nt][h * 2 + 1];
                if (ATOMIC) {
                    atomicAdd(C + (size_t)r * ldC + col, v0);
                    atomicAdd(C + (size_t)r * ldC + col + 1, v1);
                } else {
                    if (bias)  { v0 += bias[col]; v1 += bias[col + 1]; }
                    if (accum) {
                        float2 old = *reinterpret_cast<float2*>(
                            C + (size_t)r * ldC + col);
                        v0 += old.x; v1 += old.y;
                    }
                    if (SPLITOUT) {
                        __nv_bfloat162 h2, l2;
                        split2(v0, h2.x, l2.x);
                        split2(v1, h2.y, l2.y);
                        *reinterpret_cast<__nv_bfloat162*>(
                            Chi + (size_t)r * ldC + col) = h2;
                        *reinterpret_cast<__nv_bfloat162*>(
                            Clo + (size_t)r * ldC + col) = l2;
                    } else {
                        *reinterpret_cast<float2*>(C + (size_t)r * ldC + col) =
                            make_float2(v0, v1);
                    }
                }
            }
        }
    }
}

// ---- mma wrappers ---------------------------------------------------------
__global__ void __launch_bounds__(256, 2) k_mma_Q() {
    mma_body<1, 0>(g_aihi, g_ailo, g_WThi, g_WTlo, nullptr, g_Qhi, g_Qlo,
                   kH, 0, kH, kHH, 1.0f, nullptr, 0);
}
__global__ void __launch_bounds__(256, 2) k_mma_K() {
    mma_body<1, 0>(g_aihi, g_ailo, g_WThi, g_WTlo, nullptr, g_Khi, g_Klo,
                   kH, 0, kH, kHH, 1.0f, nullptr, 0);
}
__global__ void __launch_bounds__(256, 2) k_mma_V() {
    mma_body<0, 0>(g_aihi, g_ailo, g_WThi, g_WTlo, g_V, nullptr, nullptr,
                   kH, 0, kH, kHH, 1.0f, nullptr, 0);
}
__global__ void __launch_bounds__(256, 2) k_mma_el() {
    mma_body<0, 0>(g_ejhi, g_ejlo, g_WThi, g_WTlo, g_V, nullptr, nullptr,
                   k3H, 0, k3H, kHH, 1.0f, nullptr, 1);
}
__global__ void __launch_bounds__(256, 2) k_mma_rl() {
    mma_body<0, 0>(g_rbfhi, g_rbflo, g_WThi, g_WTlo, g_V, nullptr, nullptr,
                   kRBF, 0, kRBF, kHH, 1.0f, nullptr, 1);
}
__global__ void __launch_bounds__(256, 2) k_mma_logits() {
    mma_body<0, 0>(g_Qhi, g_Qlo, g_Khi, g_Klo, g_logits, nullptr, nullptr,
                   kHH, 0, kHH, kE, 0.08838834764831845f, nullptr, 0);
}
// FW = feats @ ol_w  (K-split x2, atomic into zeroed g_hi)
__global__ void __launch_bounds__(256, 2) k_mma_FW() {
    int kb = blockIdx.z * (kHH / 2);
    mma_body<0, 1>(g_Fhi, g_Flo, g_WThi, g_WTlo, g_hi, nullptr, nullptr,
                   kHH, kb, kb + kHH / 2, kH, 1.0f, nullptr, 0);
}
// msg = P @ FW  (K-split x4, atomic into ol_b-initialized g_msg)
__global__ void __launch_bounds__(256, 2) k_mma_msg() {
    int kb = blockIdx.z * (kE / 4);
    mma_body<0, 1>(g_Phi, g_Plo, g_Khi, g_Klo, g_msg, nullptr, nullptr,
                   kE, kb, kb + kE / 4, kH, 1.0f, nullptr, 0);
}

// ---------------------------------------------------------------------------
// Split kernels: fp32 -> bf16 (hi, lo)
// ---------------------------------------------------------------------------
__global__ void k_split_ai() {
    int i = blockIdx.x * 256 + threadIdx.x;
    split2(g_ai[i], g_aihi[i], g_ailo[i]);
}
__global__ void k_split_ej() {
    int i = blockIdx.x * 256 + threadIdx.x;
    split2(g_edgeij[i], g_ejhi[i], g_ejlo[i]);
}
__global__ void k_split_rbf() {
    int i = blockIdx.x * 256 + threadIdx.x;
    split2(g_rbf[i], g_rbfhi[i], g_rbflo[i]);
}
__global__ void k_split_F() {
    int i = blockIdx.x * 256 + threadIdx.x;
    split2(g_V[i], g_Fhi[i], g_Flo[i]);
}

// Weight transpose+split: W [R x C] fp32 row-major -> g_WT [C x R] bf16 hi/lo
template <int R, int C>
__global__ void k_tsplitW(const float* __restrict__ W) {
    __shared__ float tile[32][33];
    int tx = threadIdx.x, ty = threadIdx.y;      // 32 x 8
    int c0 = blockIdx.x * 32;
    int r0 = blockIdx.y * 32;
    #pragma unroll
    for (int i = 0; i < 4; i++)
        tile[ty + i * 8][tx] = W[(size_t)(r0 + ty + i * 8) * C + c0 + tx];
    __syncthreads();
    #pragma unroll
    for (int i = 0; i < 4; i++) {
        int c = c0 + ty + i * 8;
        int r = r0 + tx;
        float v = tile[tx][ty + i * 8];
        __nv_bfloat16 h, l;
        split2(v, h, l);
        g_WThi[(size_t)c * R + r] = h;
        g_WTlo[(size_t)c * R + r] = l;
    }
}

// FW [kE x kH] (g_hi) -> FW^T split [kH x kE] into g_Khi/g_Klo (dead post-logits)
__global__ void k_tsplit_FW() {
    __shared__ float tile[32][33];
    int tx = threadIdx.x, ty = threadIdx.y;      // 32 x 8
    int c0 = blockIdx.x * 32;                    // along kH
    int r0 = blockIdx.y * 32;                    // along kE
    #pragma unroll
    for (int i = 0; i < 4; i++)
        tile[ty + i * 8][tx] = g_hi[(size_t)(r0 + ty + i * 8) * kH + c0 + tx];
    __syncthreads();
    #pragma unroll
    for (int i = 0; i < 4; i++) {
        int c = c0 + ty + i * 8;
        int r = r0 + tx;
        float v = tile[tx][ty + i * 8];
        __nv_bfloat16 h, l;
        split2(v, h, l);
        g_Khi[(size_t)c * kE + r] = h;
        g_Klo[(size_t)c * kE + r] = l;
    }
}

__global__ void k_zero_FW() {
    int i = blockIdx.x * 256 + threadIdx.x;
    g_hi[i] = 0.0f;
}
__global__ void k_init_msg(const float* __restrict__ b) {
    int e = blockIdx.x, t = threadIdx.x;
    g_msg[e * kH + t] = b[t];
}

// ---------------------------------------------------------------------------
// Detect edge_indices element width (int64 vs int32).
// ---------------------------------------------------------------------------
__global__ void detect_idx_kernel(const void* __restrict__ ei) {
    const int* p = (const int*)ei;
    int looks64 = 1;
    for (int i = 0; i < 32; i++)
        if (p[2 * i + 1] != 0) looks64 = 0;
    g_is64 = looks64;
}

// ---------------------------------------------------------------------------
// prep: ai/aj = atom[tgt/src] + ew ; rbf features.  grid kE x kH
// ---------------------------------------------------------------------------
__global__ void prep_kernel(const float* __restrict__ atom,
                            const float* __restrict__ pos,
                            const float* __restrict__ ew,
                            const void* __restrict__ ei) {
    int e = blockIdx.x, t = threadIdx.x;
    __shared__ float sdist;
    __shared__ int ssrc, stgt;
    if (t == 0) {
        int s, g;
        if (g_is64) {
            const long long* p = (const long long*)ei;
            s = (int)p[e];  g = (int)p[kE + e];
        } else {
            const int* p = (const int*)ei;
            s = p[e];  g = p[kE + e];
        }
        ssrc = s; stgt = g;
        g_src[e] = s; g_tgt[e] = g;
        float dx = pos[g * 3 + 0] - pos[s * 3 + 0];
        float dy = pos[g * 3 + 1] - pos[s * 3 + 1];
        float dz = pos[g * 3 + 2] - pos[s * 3 + 2];
        sdist = sqrtf(dx * dx + dy * dy + dz * dz);
    }
    __syncthreads();
    float w = ew[e];
    g_ai[e * kH + t] = atom[stgt * kH + t] + w;
    g_aj[e * kH + t] = atom[ssrc * kH + t] + w;
    if (t < kRBF) {
        float d  = sdist;
        float x  = d * 0.1f;
        float x3 = x * x * x, x4 = x3 * x, x5 = x4 * x;
        float cut = (x < 1.0f) ? (1.0f - 6.0f * x5 + 15.0f * x4 - 10.0f * x3) : 0.0f;
        float em10 = expf(-10.0f);
        float step = (em10 - 1.0f) / 63.0f;
        float center = 1.0f + (float)t * step;
        float wd = 0.5f / ((1.0f - em10) / 64.0f);
        wd = wd * wd;
        float diff = expf(-d) - center;
        g_rbf[e * kRBF + t] = cut * expf(-wd * diff * diff);
    }
}

// edge_ij = [hi+hj, hi-hj, hi*hj]   grid: kE x kH
__global__ void edgeij_kernel() {
    int e = blockIdx.x, t = threadIdx.x;
    float hi = g_hi[e * kH + t];
    float hj = g_hj[e * kH + t];
    size_t b = (size_t)e * k3H;
    g_edgeij[b + t]          = hi + hj;
    g_edgeij[b + kH + t]     = hi - hj;
    g_edgeij[b + 2 * kH + t] = hi * hj;
}

// ---------------------------------------------------------------------------
// FFMA GEMM body (small GEMMs: hi, hj, f1-3)
// ---------------------------------------------------------------------------
template <int ACT>
__device__ __forceinline__
void gemm_body(const float* __restrict__ A, const float* __restrict__ B,
               float* __restrict__ C, int M, int Nd, int Kd,
               const float* __restrict__ bias) {
    constexpr int BM = 128, BN = 128, BK = 16;
    __shared__ __align__(16) float As[BK][BM + 4];
    __shared__ __align__(16) float Bs[BK][BN + 4];
    int tid = threadIdx.x;
    int tx = tid & 15, ty = tid >> 4;
    int m0 = blockIdx.y * BM, n0 = blockIdx.x * BN;
    float acc[8][8] = {};

    for (int k0 = 0; k0 < Kd; k0 += BK) {
        #pragma unroll
        for (int i = 0; i < 2; i++) {
            int f = tid + i * 256;
            int row = f >> 2, c4 = (f & 3) * 4;
            float4 av = *reinterpret_cast<const float4*>(
                &A[(size_t)(m0 + row) * Kd + k0 + c4]);
            As[c4 + 0][row] = av.x; As[c4 + 1][row] = av.y;
            As[c4 + 2][row] = av.z; As[c4 + 3][row] = av.w;
        }
        #pragma unroll
        for (int i = 0; i < 2; i++) {
            int f = tid + i * 256;
            int row = f >> 5, c4 = (f & 31) * 4;
            float4 bv = *reinterpret_cast<const float4*>(
                &B[(size_t)(k0 + row) * Nd + n0 + c4]);
            *reinterpret_cast<float4*>(&Bs[row][c4]) = bv;
        }
        __syncthreads();
        #pragma unroll
        for (int k = 0; k < BK; k++) {
            float4 a0 = *reinterpret_cast<const float4*>(&As[k][ty * 8]);
            float4 a1 = *reinterpret_cast<const float4*>(&As[k][ty * 8 + 4]);
            float4 b0 = *reinterpret_cast<const float4*>(&Bs[k][tx * 8]);
            float4 b1 = *reinterpret_cast<const float4*>(&Bs[k][tx * 8 + 4]);
            float a[8] = {a0.x, a0.y, a0.z, a0.w, a1.x, a1.y, a1.z, a1.w};
            float b[8] = {b0.x, b0.y, b0.z, b0.w, b1.x, b1.y, b1.z, b1.w};
            #pragma unroll
            for (int i = 0; i < 8; i++)
                #pragma unroll
                for (int j = 0; j < 8; j++)
                    acc[i][j] = fmaf(a[i], b[j], acc[i][j]);
        }
        __syncthreads();
    }

    #pragma unroll
    for (int i = 0; i < 8; i++) {
        int m = m0 + ty * 8 + i;
        #pragma unroll
        for (int j = 0; j < 8; j++) {
            int n = n0 + tx * 8 + j;
            float v = acc[i][j];
            if (bias) v += bias[n];
            if (ACT)  v = softplus_f(v);
            C[(size_t)m * Nd + n] = v;
        }
    }
}

__global__ __launch_bounds__(256) void k_gemm_hi(const float* __restrict__ W,
                                                 const float* __restrict__ b) {
    gemm_body<0>(g_ai, W, g_hi, kE, kH, kH, b);
}
__global__ __launch_bounds__(256) void k_gemm_hj(const float* __restrict__ W,
                                                 const float* __restrict__ b) {
    gemm_body<0>(g_aj, W, g_hj, kE, kH, kH, b);
}
__global__ __launch_bounds__(256) void k_gemm_f1(const float* __restrict__ W,
                                                 const float* __restrict__ b) {
    gemm_body<1>(g_ln0, W, g_t1, kN, kH, kH, b);
}
__global__ __launch_bounds__(256) void k_gemm_f2(const float* __restrict__ W,
                                                 const float* __restrict__ b) {
    gemm_body<1>(g_t1, W, g_t2, kN, kH, kH, b);
}
__global__ __launch_bounds__(256) void k_gemm_f3(const float* __restrict__ W,
                                                 const float* __restrict__ b) {
    gemm_body<1>(g_t2, W, g_t3, kN, kH, kH, b);
}

// ---------------------------------------------------------------------------
// Per-row segmented softmax over columns, groups = src[col].
// Pass 3 writes split-bf16 P directly. grid: kE x 256
// ---------------------------------------------------------------------------
__global__ void softmax_kernel() {
    __shared__ unsigned int smax[kN];
    __shared__ float ssum[kN];
    __shared__ int ssrc[kE];
    const int T = 256;
    int row = blockIdx.x, t = threadIdx.x;
    for (int i = t; i < kN; i += T) { smax[i] = 0u; ssum[i] = 0.0f; }
    for (int i = t; i < kE; i += T) ssrc[i] = g_src[i];
    __syncthreads();
    const float* L = g_logits + (size_t)row * kE;
    for (int b = t; b < kE; b += T) {
        unsigned u = __float_as_uint(L[b]);
        u = (u & 0x80000000u) ? ~u : (u | 0x80000000u);
        atomicMax(&smax[ssrc[b]], u);
    }
    __syncthreads();
    for (int b = t; b < kE; b += T) {
        unsigned u = smax[ssrc[b]];
        float m = (u & 0x80000000u) ? __uint_as_float(u & 0x7FFFFFFFu)
                                    : __uint_as_float(~u);
        atomicAdd(&ssum[ssrc[b]], __expf(L[b] - m));
    }
    __syncthreads();
    for (int b = t; b < kE; b += T) {
        int s = ssrc[b];
        unsigned u = smax[s];
        float m = (u & 0x80000000u) ? __uint_as_float(u & 0x7FFFFFFFu)
                                    : __uint_as_float(~u);
        float p = __expf(L[b] - m) / ssum[s];
        __nv_bfloat16 h, l;
        split2(p, h, l);
        g_Phi[(size_t)row * kE + b] = h;
        g_Plo[(size_t)row * kE + b] = l;
    }
}

// feats init: V += el_b + rl_b (broadcast over columns)
__global__ void feats_bias_kernel(const float* __restrict__ el_b,
                                  const float* __restrict__ rl_b) {
    int i = blockIdx.x * blockDim.x + threadIdx.x;
    int c = i & (kHH - 1);
    g_V[i] += el_b[c] + rl_b[c];
}

__global__ void zero_agg_kernel() {
    int i = blockIdx.x * blockDim.x + threadIdx.x;
    g_agg[i] = 0.0f;
}

// segment_sum(msg, tgt) via atomics. grid kE x kH
__global__ void scatter_kernel() {
    int e = blockIdx.x, t = threadIdx.x;
    atomicAdd(&g_agg[g_tgt[e] * kH + t], g_msg[e * kH + t]);
}

// ---------------------------------------------------------------------------
// LayerNorm over H=128, one block (128 threads) per node.
// ---------------------------------------------------------------------------
__device__ __forceinline__ float blockSum128(float v) {
    __shared__ float sw[4];
    __syncthreads();
    int lane = threadIdx.x & 31, wid = threadIdx.x >> 5;
    #pragma unroll
    for (int o = 16; o; o >>= 1) v += __shfl_down_sync(0xffffffffu, v, o);
    if (lane == 0) sw[wid] = v;
    __syncthreads();
    if (threadIdx.x == 0) sw[0] = sw[0] + sw[1] + sw[2] + sw[3];
    __syncthreads();
    return sw[0];
}

__device__ __forceinline__ void ln_body(const float* __restrict__ in,
                                        float* __restrict__ out,
                                        const float* __restrict__ gw,
                                        const float* __restrict__ gb) {
    int n = blockIdx.x, t = threadIdx.x;
    float x = in[n * kH + t];
    float mu = blockSum128(x) * (1.0f / kH);
    float d = x - mu;
    float var = blockSum128(d * d) * (1.0f / kH);
    out[n * kH + t] = d * rsqrtf(var + 1e-5f) * gw[t] + gb[t];
}

__global__ void k_ln_agg(const float* __restrict__ gw, const float* __restrict__ gb) {
    ln_body(g_agg, g_ln0, gw, gb);
}
__global__ void k_ln_out(float* __restrict__ out,
                         const float* __restrict__ gw, const float* __restrict__ gb) {
    ln_body(g_t3, out, gw, gb);
}

// ---------------------------------------------------------------------------
// Launch
// ---------------------------------------------------------------------------
extern "C" void kernel_launch(void* const* d_in, const int* in_sizes, int n_in,
                              void* d_out, int out_size) {
    const float* atom  = (const float*)d_in[0];
    const float* pos   = (const float*)d_in[1];
    const float* ew    = (const float*)d_in[2];
    const void*  ei    = d_in[3];
    const float* Wq    = (const float*)d_in[4];
    const float* Wk    = (const float*)d_in[5];
    const float* Wv    = (const float*)d_in[6];
    const float* li_w  = (const float*)d_in[7];
    const float* li_b  = (const float*)d_in[8];
    const float* lj_w  = (const float*)d_in[9];
    const float* lj_b  = (const float*)d_in[10];
    const float* el_w  = (const float*)d_in[11];
    const float* el_b  = (const float*)d_in[12];
    const float* rl_w  = (const float*)d_in[13];
    const float* rl_b  = (const float*)d_in[14];
    const float* ol_w  = (const float*)d_in[15];
    const float* ol_b  = (const float*)d_in[16];
    const float* ln_g  = (const float*)d_in[17];
    const float* ln_b  = (const float*)d_in[18];
    const float* f1_w  = (const float*)d_in[19];
    const float* f1_b  = (const float*)d_in[20];
    const float* f2_w  = (const float*)d_in[21];
    const float* f2_b  = (const float*)d_in[22];
    const float* f3_w  = (const float*)d_in[23];
    const float* f3_b  = (const float*)d_in[24];
    float* out = (float*)d_out;

    // Idempotent, capture-legal; called unconditionally (no static guards).
    cudaFuncSetAttribute(k_mma_Q,      cudaFuncAttributeMaxDynamicSharedMemorySize, MMA_SMEM);
    cudaFuncSetAttribute(k_mma_K,      cudaFuncAttributeMaxDynamicSharedMemorySize, MMA_SMEM);
    cudaFuncSetAttribute(k_mma_V,      cudaFuncAttributeMaxDynamicSharedMemorySize, MMA_SMEM);
    cudaFuncSetAttribute(k_mma_el,     cudaFuncAttributeMaxDynamicSharedMemorySize, MMA_SMEM);
    cudaFuncSetAttribute(k_mma_rl,     cudaFuncAttributeMaxDynamicSharedMemorySize, MMA_SMEM);
    cudaFuncSetAttribute(k_mma_logits, cudaFuncAttributeMaxDynamicSharedMemorySize, MMA_SMEM);
    cudaFuncSetAttribute(k_mma_FW,     cudaFuncAttributeMaxDynamicSharedMemorySize, MMA_SMEM);
    cudaFuncSetAttribute(k_mma_msg,    cudaFuncAttributeMaxDynamicSharedMemorySize, MMA_SMEM);

    detect_idx_kernel<<<1, 1>>>(ei);
    prep_kernel<<<kE, kH>>>(atom, pos, ew, ei);

    // QKV via tensor cores (split ai once; weights transposed+split in turn)
    k_split_ai<<<(kE * kH) / 256, 256>>>();
    dim3 gQKV(kHH / 128, kE / 128);   // 8 x 32
    k_tsplitW<kH, kHH><<<dim3(kHH / 32, kH / 32), dim3(32, 8)>>>(Wq);
    k_mma_Q<<<gQKV, 256, MMA_SMEM>>>();
    k_tsplitW<kH, kHH><<<dim3(kHH / 32, kH / 32), dim3(32, 8)>>>(Wk);
    k_mma_K<<<gQKV, 256, MMA_SMEM>>>();
    k_tsplitW<kH, kHH><<<dim3(kHH / 32, kH / 32), dim3(32, 8)>>>(Wv);
    k_mma_V<<<gQKV, 256, MMA_SMEM>>>();

    dim3 gH(kH / 128, kE / 128);      // 1 x 32
    k_gemm_hi<<<gH, 256>>>(li_w, li_b);
    k_gemm_hj<<<gH, 256>>>(lj_w, lj_b);
    edgeij_kernel<<<kE, kH>>>();

    // logits = scale * Q @ K^T  (pipelined split-bf16 mma)
    k_mma_logits<<<dim3(kE / 128, kE / 128), 256, MMA_SMEM>>>();

    softmax_kernel<<<kE, 256>>>();    // writes split-bf16 P

    // feats = V + el_b + rl_b + edge_ij@el_w + rbf@rl_w   (in g_V)
    feats_bias_kernel<<<(kE * kHH) / 256, 256>>>(el_b, rl_b);
    k_split_ej<<<(kE * k3H) / 256, 256>>>();
    k_tsplitW<k3H, kHH><<<dim3(kHH / 32, k3H / 32), dim3(32, 8)>>>(el_w);
    k_mma_el<<<gQKV, 256, MMA_SMEM>>>();
    k_split_rbf<<<(kE * kRBF) / 256, 256>>>();
    k_tsplitW<kRBF, kHH><<<dim3(kHH / 32, kRBF / 32), dim3(32, 8)>>>(rl_w);
    k_mma_rl<<<gQKV, 256, MMA_SMEM>>>();

    // FW = feats @ ol_w   (associativity: msg = P @ FW + ol_b)
    k_split_F<<<(kE * kHH) / 256, 256>>>();
    k_tsplitW<kHH, kH><<<dim3(kH / 32, kHH / 32), dim3(32, 8)>>>(ol_w);
    k_zero_FW<<<(kE * kH) / 256, 256>>>();
    k_mma_FW<<<dim3(1, kE / 128, 2), 256, MMA_SMEM>>>();

    // FW -> FW^T split (B operand), stored in dead K buffers
    k_tsplit_FW<<<dim3(kH / 32, kE / 32), dim3(32, 8)>>>();

    // msg = P @ FW + ol_b  (K-split x4, atomic accumulate)
    k_init_msg<<<kE, kH>>>(ol_b);
    k_mma_msg<<<dim3(1, kE / 128, 4), 256, MMA_SMEM>>>();

    zero_agg_kernel<<<(kN * kH) / 256, 256>>>();
    scatter_kernel<<<kE, kH>>>();

    k_ln_agg<<<kN, kH>>>(ln_g, ln_b);

    dim3 gF(kH / 128, kN / 128);      // 1 x 4
    k_gemm_f1<<<gF, 256>>>(f1_w, f1_b);
    k_gemm_f2<<<gF, 256>>>(f2_w, f2_b);
    k_gemm_f3<<<gF, 256>>>(f3_w, f3_b);

    k_ln_out<<<kN, kH>>>(out, ln_g, ln_b);
}